// round 10
// baseline (speedup 1.0000x reference)
#include <cuda_runtime.h>
#include <cuda_fp16.h>
#include <math.h>
#include <stdint.h>

#define B_ 4
#define T_ 2048
#define D_ 512
#define M_ (B_*T_)   /* 8192 */

/* ------------ static device scratch (no allocations) ------------ */
__device__ float  g_xpe[(size_t)M_*D_];          // x + PE (fp32, residuals)
__device__ __half g_xpe_h[(size_t)M_*D_];        // fp16 GEMM input
__device__ float  g_xp [(size_t)4*M_*3*D_];      // wih @ xpe + bih
__device__ float  g_q  [(size_t)4*M_*D_];
__device__ float  g_kk [(size_t)4*M_*D_];
__device__ float  g_v  [(size_t)4*M_*D_];
__device__ __half g_comb_h[(size_t)4*M_*2*D_];   // [gru | attn] fp16
__device__ float  g_thr[(size_t)4*M_*D_];        // beat (fp32 GEMM out)
__device__ __half g_thr_h[(size_t)4*M_*D_];      // LN(beat+xpe) fp16
__device__ float  g_mix[(size_t)M_*D_];
/* fp16 weights */
__device__ __half g_wih_h [(size_t)4*3*D_*D_];
__device__ __half g_wq_h  [(size_t)4*D_*D_];
__device__ __half g_wk_h  [(size_t)4*D_*D_];
__device__ __half g_wv_h  [(size_t)4*D_*D_];
__device__ __half g_wbt_h [(size_t)4*D_*2*D_];
__device__ __half g_wmx_h [(size_t)D_*4*D_];
/* hidden-state payloads: (tag<<32 | f32 bits), [2 buf][4 kt][4 b][512 j] */
__device__ __align__(128) unsigned long long g_hp[2*4*4*512];

__device__ __forceinline__ uint32_t packh2(float lo, float hi) {
    uint32_t d; asm("cvt.rn.f16x2.f32 %0, %1, %2;" : "=r"(d) : "f"(hi), "f"(lo));
    return d;
}
__device__ __forceinline__ float fsig(float x) {
    return __fdividef(1.f, 1.f + __expf(-x));
}
__device__ __forceinline__ void cp16(void* s, const void* g) {
    uint32_t a = (uint32_t)__cvta_generic_to_shared(s);
    asm volatile("cp.async.cg.shared.global [%0], [%1], 16;" :: "r"(a), "l"(g));
}
__device__ __forceinline__ unsigned long long ldrx(const unsigned long long* p) {
    unsigned long long v;
    asm volatile("ld.relaxed.gpu.global.b64 %0, [%1];" : "=l"(v) : "l"(p) : "memory");
    return v;
}
__device__ __forceinline__ void strx(unsigned long long* p, unsigned long long v) {
    asm volatile("st.relaxed.gpu.global.b64 [%0], %1;" :: "l"(p), "l"(v) : "memory");
}
#define MMA_F16A(C, A0, A1, A2, A3, B0, B1) \
    asm volatile("mma.sync.aligned.m16n8k16.row.col.f32.f16.f16.f32 " \
        "{%0,%1,%2,%3},{%4,%5,%6,%7},{%8,%9},{%0,%1,%2,%3};" \
        : "+f"((C)[0]), "+f"((C)[1]), "+f"((C)[2]), "+f"((C)[3]) \
        : "r"(A0), "r"(A1), "r"(A2), "r"(A3), "r"(B0), "r"(B1))
#define MMA_F16(C, FR, B0, B1) MMA_F16A(C, (FR).x, (FR).y, (FR).z, (FR).w, B0, B1)

/* ---------------------------- init ------------------------------ */
__global__ void init_kernel() {
    int i = blockIdx.x * 256 + threadIdx.x;
    if (i < 2*4*4*512) g_hp[i] = 0ull;
}

/* -------------------- f32 -> f16 convert ------------------------- */
__global__ void f2h_kernel(const float* __restrict__ in, __half* __restrict__ out, int n4) {
    int i = blockIdx.x * 256 + threadIdx.x;
    if (i < n4) {
        float4 v = ((const float4*)in)[i];
        __half2 h0 = __floats2half2_rn(v.x, v.y);
        __half2 h1 = __floats2half2_rn(v.z, v.w);
        ((__half2*)out)[2*i]   = h0;
        ((__half2*)out)[2*i+1] = h1;
    }
}

/* -------------------- positional encoding ----------------------- */
__global__ void pe_add_kernel(const float* __restrict__ x) {
    int idx = blockIdx.x * 256 + threadIdx.x;   // 0 .. T*D-1
    int t = idx >> 9;
    int d = idx & 511;
    const float kfac = -9.210340371976184f / 512.0f;
    float dv  = expf((float)(d & ~1) * kfac);
    float arg = (float)t * dv;
    float pe  = (d & 1) ? cosf(arg) : sinf(arg);
    int slot = d >> 7;
    int off  = d & 127;
    int c    = 5 + slot;
    float ph = ((float)(t % c) / (float)c) * 6.283185307179586f;
    float tv = (off < 64) ? sinf(ph * (float)(off + 1)) : cosf(ph * (float)(off - 63));
    float tot = 0.5f * pe + 0.5f * tv;
    #pragma unroll
    for (int b = 0; b < B_; ++b) {
        float v = x[(size_t)b*(T_*D_) + idx] + tot;
        g_xpe  [(size_t)b*(T_*D_) + idx] = v;
        g_xpe_h[(size_t)b*(T_*D_) + idx] = __float2half(v);
    }
}

/* --------- fp16 tensor-core NT GEMM, cp.async 3-stage ------------ */
__global__ void __launch_bounds__(256)
gemm_kernel(const __half* __restrict__ A, size_t sAz, size_t sAm, size_t sAchunk,
            const __half* __restrict__ W, size_t sWz, int K,
            const float* __restrict__ bias, size_t sBz,
            float* __restrict__ C, size_t sCz, size_t sCm)
{
    extern __shared__ __half hsm[];
    __half* As0 = hsm;             // [3][128][40]
    __half* Bs0 = hsm + 15360;
#define AS(s,r,k) As0[(s)*5120 + (r)*40 + (k)]
#define BS(s,r,k) Bs0[(s)*5120 + (r)*40 + (k)]
    const int z  = blockIdx.z;
    const int m0 = blockIdx.x * 128;
    const int n0 = blockIdx.y * 128;
    const int tid = threadIdx.x;
    const int hr = tid >> 1;
    const int hc = (tid & 1) * 16;
    const int warp = tid >> 5;
    const int lane = tid & 31;
    const int wm = warp >> 1;
    const int wn = warp & 1;
    const int gid = lane >> 2;
    const int tig = lane & 3;

    const __half* Az = A + (size_t)z * sAz;
    const __half* Wz = W + (size_t)z * sWz;

    float acc[2][8][4];
    #pragma unroll
    for (int mf = 0; mf < 2; ++mf)
        #pragma unroll
        for (int nf = 0; nf < 8; ++nf)
            #pragma unroll
            for (int q = 0; q < 4; ++q) acc[mf][nf][q] = 0.f;

    const int nt = K >> 5;
    {
        const __half* ap = Az + (size_t)(m0 + hr) * sAm + hc;
        cp16(&AS(0,hr,hc), ap); cp16(&AS(0,hr,hc+8), ap + 8);
        const __half* wp = Wz + (size_t)(n0 + hr) * K + hc;
        cp16(&BS(0,hr,hc), wp); cp16(&BS(0,hr,hc+8), wp + 8);
        asm volatile("cp.async.commit_group;");
    }
    if (nt > 1) {
        const __half* ap = Az + (size_t)(m0 + hr) * sAm + 32 + hc;
        cp16(&AS(1,hr,hc), ap); cp16(&AS(1,hr,hc+8), ap + 8);
        const __half* wp = Wz + (size_t)(n0 + hr) * K + 32 + hc;
        cp16(&BS(1,hr,hc), wp); cp16(&BS(1,hr,hc+8), wp + 8);
        asm volatile("cp.async.commit_group;");
    }
    for (int kt = 0; kt < nt; ++kt) {
        if (kt + 1 < nt) asm volatile("cp.async.wait_group 1;");
        else             asm volatile("cp.async.wait_group 0;");
        __syncthreads();
        if (kt + 2 < nt) {
            int j0 = (kt + 2) * 32;
            int ps = (kt + 2) % 3;
            const __half* ap = Az + (size_t)(m0 + hr) * sAm + (size_t)(j0 >> 9) * sAchunk + (j0 & 511) + hc;
            cp16(&AS(ps,hr,hc), ap); cp16(&AS(ps,hr,hc+8), ap + 8);
            const __half* wp = Wz + (size_t)(n0 + hr) * K + j0 + hc;
            cp16(&BS(ps,hr,hc), wp); cp16(&BS(ps,hr,hc+8), wp + 8);
            asm volatile("cp.async.commit_group;");
        }
        const int s = kt % 3;
        #pragma unroll
        for (int ks = 0; ks < 2; ++ks) {
            const int kb = ks * 16;
            uint32_t af[2][4];
            #pragma unroll
            for (int mf = 0; mf < 2; ++mf) {
                int m = wm*32 + mf*16 + gid;
                af[mf][0] = *(const uint32_t*)&AS(s, m,   kb + 2*tig);
                af[mf][1] = *(const uint32_t*)&AS(s, m+8, kb + 2*tig);
                af[mf][2] = *(const uint32_t*)&AS(s, m,   kb + 2*tig + 8);
                af[mf][3] = *(const uint32_t*)&AS(s, m+8, kb + 2*tig + 8);
            }
            #pragma unroll
            for (int nf = 0; nf < 8; ++nf) {
                int n = wn*64 + nf*8 + gid;
                uint32_t b0v = *(const uint32_t*)&BS(s, n, kb + 2*tig);
                uint32_t b1v = *(const uint32_t*)&BS(s, n, kb + 2*tig + 8);
                MMA_F16A(acc[0][nf], af[0][0], af[0][1], af[0][2], af[0][3], b0v, b1v);
                MMA_F16A(acc[1][nf], af[1][0], af[1][1], af[1][2], af[1][3], b0v, b1v);
            }
        }
    }

    float* Cz = C + (size_t)z * sCz;
    #pragma unroll
    for (int mf = 0; mf < 2; ++mf) {
        int r0 = m0 + wm*32 + mf*16 + gid;
        #pragma unroll
        for (int nf = 0; nf < 8; ++nf) {
            int col = n0 + wn*64 + nf*8 + 2*tig;
            float bb0 = 0.f, bb1 = 0.f;
            if (bias) {
                bb0 = bias[(size_t)z*sBz + col];
                bb1 = bias[(size_t)z*sBz + col + 1];
            }
            float2 o0 = make_float2(acc[mf][nf][0] + bb0, acc[mf][nf][1] + bb1);
            float2 o1 = make_float2(acc[mf][nf][2] + bb0, acc[mf][nf][3] + bb1);
            *(float2*)(Cz + (size_t)r0      * sCm + col) = o0;
            *(float2*)(Cz + (size_t)(r0+8)  * sCm + col) = o1;
        }
    }
#undef AS
#undef BS
}

/* --------------------------- GRU --------------------------------
   32 CTAs: blockIdx = kt*8 + c. CTA owns hidden units c*64..c*64+63
   (3 gates -> 192 rows), full weight slice as fp16 MMA fragments in
   SMEM (196KB). k-split over 8 warps; consumer warp w polls exactly
   ONE producer CTA (c'=w). Payload handoff as in R7. All 256 threads
   compute gates (64 units x 4 batches). Two barriers per step.     */
__global__ void __launch_bounds__(256, 1)
gru_kernel(const float* __restrict__ whh, const float* __restrict__ bhh)
{
    extern __shared__ float sm[];
    uint4* sWf  = (uint4*)sm;                 // 12288 x 16B = 196608B
    float* sRed = sm + 49152;                 // [4 b][192 row] pitch 10 = 30720B
    float* sBhh = sm + 49152 + 7680;          // 192 floats
    /* total = 228096 B */

    const int tid  = threadIdx.x;
    const int kt   = blockIdx.x >> 3;
    const int c    = blockIdx.x & 7;
    const int lane = tid & 31;
    const int w    = tid >> 5;
    const int gid  = lane >> 2;
    const int tig  = lane & 3;

    /* ---- one-time: build fp16 A fragments from whh ----
       sWf[(ks*12 + mt)*32 + lane]; rows rr = mt*16 + gid (+8),
       gate g = mt>>2, local unit uu = (mt&3)*16 + gid.           */
    const float* wkp = whh + (size_t)kt * (1536*512);
    for (int e = tid; e < 12288; e += 256) {
        int el = e & 31;
        int mt = (e >> 5) % 12;
        int ks = e / 384;
        int eg = el >> 2, et = el & 3;
        int g  = mt >> 2;
        int uu = (mt & 3)*16 + eg;
        const float* w0 = wkp + (size_t)(g*512 + c*64 + uu) * 512;
        const float* w1 = w0 + 8*512;
        int k0 = ks*16 + 2*et;
        float2 p0 = *(const float2*)(w0 + k0);
        float2 p1 = *(const float2*)(w1 + k0);
        float2 p2 = *(const float2*)(w0 + k0 + 8);
        float2 p3 = *(const float2*)(w1 + k0 + 8);
        uint4 fr;
        fr.x = packh2(p0.x, p0.y);
        fr.y = packh2(p1.x, p1.y);
        fr.z = packh2(p2.x, p2.y);
        fr.w = packh2(p3.x, p3.y);
        sWf[e] = fr;
    }
    if (tid < 192) {
        int g = tid >> 6, uu = tid & 63;
        sBhh[tid] = bhh[kt*1536 + g*512 + c*64 + uu];
    }
    __syncthreads();

    const int uu   = tid & 63;      // local unit (gate role)
    const int gb   = tid >> 6;      // batch (gate role)
    const int unit = c*64 + uu;
    const int need = (gid < 4);
    float hold = 0.f;
    const float bR = sBhh[uu], bZ = sBhh[64+uu], bN = sBhh[128+uu];

    for (int t = 0; t < T_; ++t) {
        /* xp prefetch (latency hidden under the payload poll) */
        const float* xp = g_xp + ((size_t)(kt*M_ + gb*T_ + t))*1536 + unit;
        float xr = __ldg(xp), xz = __ldg(xp + 512), xn = __ldg(xp + 1024);

        /* poll the 16 payloads this lane consumes (ONE producer CTA) */
        unsigned long long pl[4][4];
        #pragma unroll
        for (int i = 0; i < 4; ++i)
            #pragma unroll
            for (int q = 0; q < 4; ++q) pl[i][q] = 0ull;
        {
            const unsigned long long* hb =
                g_hp + ((size_t)(t & 1) * 4 + kt) * 2048 + (size_t)gid * 512;
            const uint32_t tag = (uint32_t)t;
            for (;;) {
                int ok = 1;
                if (need) {
                    #pragma unroll
                    for (int i = 0; i < 4; ++i) {
                        int k0 = ((w << 2) + i) * 16 + 2 * tig;
                        pl[i][0] = ldrx(hb + k0);
                        pl[i][1] = ldrx(hb + k0 + 1);
                        pl[i][2] = ldrx(hb + k0 + 8);
                        pl[i][3] = ldrx(hb + k0 + 9);
                        #pragma unroll
                        for (int q = 0; q < 4; ++q)
                            ok &= ((uint32_t)(pl[i][q] >> 32) == tag);
                    }
                }
                if (__all_sync(0xffffffffu, ok)) break;
            }
        }
        /* b fragments */
        uint32_t b0[4], b1[4];
        #pragma unroll
        for (int i = 0; i < 4; ++i) {
            b0[i] = packh2(__uint_as_float((uint32_t)pl[i][0]),
                           __uint_as_float((uint32_t)pl[i][1]));
            b1[i] = packh2(__uint_as_float((uint32_t)pl[i][2]),
                           __uint_as_float((uint32_t)pl[i][3]));
        }
        /* 12 m-tiles x 4 ksteps; STS partials (pitch-10 sRed) */
        #pragma unroll
        for (int mt = 0; mt < 12; ++mt) {
            float acc[4] = {0.f, 0.f, 0.f, 0.f};
            #pragma unroll
            for (int i = 0; i < 4; ++i) {
                uint4 fr = sWf[(((w << 2) + i)*12 + mt)*32 + lane];
                MMA_F16(acc, fr, b0[i], b1[i]);
            }
            if (tig < 2) {
                int rr = mt*16 + gid;
                int bb = 2*tig;
                sRed[((bb  )*192 + rr    )*10 + w] = acc[0];
                sRed[((bb+1)*192 + rr    )*10 + w] = acc[1];
                sRed[((bb  )*192 + rr + 8)*10 + w] = acc[2];
                sRed[((bb+1)*192 + rr + 8)*10 + w] = acc[3];
            }
        }
        __syncthreads();   /* partials visible */

        /* gates: every thread owns (uu, gb) */
        const float2* pr = (const float2*)(sRed + ((gb*192 +       uu)*10));
        const float2* pz = (const float2*)(sRed + ((gb*192 +  64 + uu)*10));
        const float2* pn = (const float2*)(sRed + ((gb*192 + 128 + uu)*10));
        float2 a0 = pr[0], a1 = pr[1], a2 = pr[2], a3 = pr[3];
        float2 c0 = pz[0], c1 = pz[1], c2 = pz[2], c3 = pz[3];
        float2 d0 = pn[0], d1 = pn[1], d2 = pn[2], d3 = pn[3];
        __syncthreads();   /* sRed safe to rewrite next step */

        float hr = ((a0.x+a0.y)+(a1.x+a1.y)) + ((a2.x+a2.y)+(a3.x+a3.y)) + bR;
        float hz = ((c0.x+c0.y)+(c1.x+c1.y)) + ((c2.x+c2.y)+(c3.x+c3.y)) + bZ;
        float hn = ((d0.x+d0.y)+(d1.x+d1.y)) + ((d2.x+d2.y)+(d3.x+d3.y)) + bN;
        float r = fsig(xr + hr);
        float z = fsig(xz + hz);
        float ax = xn + r * hn;
        float n = 1.f - __fdividef(2.f, __expf(2.f*ax) + 1.f);
        float hnew = (1.f - z) * n + z * hold;
        hold = hnew;
        unsigned long long pay =
            ((unsigned long long)(uint32_t)(t + 1) << 32) |
            (unsigned long long)__float_as_uint(hnew);
        strx(g_hp + ((size_t)((t + 1) & 1) * 4 + kt) * 2048 +
             (size_t)gb * 512 + unit, pay);
        g_comb_h[((size_t)(kt*M_ + gb*T_ + t)) * 1024 + unit] = __float2half(hnew);
    }
}

/* ------------------------- attention ---------------------------- */
__global__ void attn_kernel() {
    int gw   = blockIdx.x * 8 + (threadIdx.x >> 5);
    int lane = threadIdx.x & 31;
    int t  = gw & (T_ - 1);
    int kb = gw >> 11;
    int b  = kb & 3;
    int kt = kb >> 2;
    int c  = 5 + kt;
    int L  = min(c, t + 1);
    size_t rowbase = (size_t)kt * M_ + (size_t)b * T_;
    const float* qp = g_q + (rowbase + t) * D_;
    float4 qv[4];
    #pragma unroll
    for (int e = 0; e < 4; ++e) qv[e] = *(const float4*)(qp + 4*lane + 128*e);

    float sc[8];
    float smax = -1e30f;
    #pragma unroll
    for (int s0 = 0; s0 < 8; ++s0) {
        if (s0 < L) {
            const float* kp = g_kk + (rowbase + t - s0) * D_;
            float a = 0.f;
            #pragma unroll
            for (int e = 0; e < 4; ++e) {
                float4 kv = *(const float4*)(kp + 4*lane + 128*e);
                a += qv[e].x*kv.x + qv[e].y*kv.y + qv[e].z*kv.z + qv[e].w*kv.w;
            }
            #pragma unroll
            for (int off = 16; off; off >>= 1) a += __shfl_xor_sync(0xffffffffu, a, off);
            a *= 0.044194173824159216f;
            sc[s0] = a;
            smax = fmaxf(smax, a);
        }
    }
    float denom = 0.f;
    float4 acc[4];
    #pragma unroll
    for (int e = 0; e < 4; ++e) acc[e] = make_float4(0.f, 0.f, 0.f, 0.f);
    #pragma unroll
    for (int s0 = 0; s0 < 8; ++s0) {
        if (s0 < L) {
            float p = expf(sc[s0] - smax);
            denom += p;
            const float* vp = g_v + (rowbase + t - s0) * D_;
            #pragma unroll
            for (int e = 0; e < 4; ++e) {
                float4 vv = *(const float4*)(vp + 4*lane + 128*e);
                acc[e].x += p*vv.x; acc[e].y += p*vv.y;
                acc[e].z += p*vv.z; acc[e].w += p*vv.w;
            }
        }
    }
    float inv = 1.f / denom;
    __half* op = g_comb_h + (rowbase + t) * 1024 + 512;
    #pragma unroll
    for (int e = 0; e < 4; ++e) {
        __half2 h0 = __floats2half2_rn(acc[e].x*inv, acc[e].y*inv);
        __half2 h1 = __floats2half2_rn(acc[e].z*inv, acc[e].w*inv);
        *(__half2*)(op + 4*lane + 128*e)     = h0;
        *(__half2*)(op + 4*lane + 128*e + 2) = h1;
    }
}

/* ----------------- layernorm (+residual) ------------------------ */
__global__ void ln_kernel(const float* __restrict__ inp, const float* __restrict__ res,
                          const float* __restrict__ gg, const float* __restrict__ bb,
                          float* __restrict__ outf, __half* __restrict__ outh, int zdiv)
{
    int row  = blockIdx.x * 8 + (threadIdx.x >> 5);
    int lane = threadIdx.x & 31;
    int z    = zdiv ? (row / zdiv) : 0;
    int rrow = zdiv ? (row % zdiv) : row;
    const float* ip = inp + (size_t)row * 512;
    const float* rp = res + (size_t)rrow * 512;
    float4 v[4];
    float s = 0.f;
    #pragma unroll
    for (int e = 0; e < 4; ++e) {
        float4 a  = *(const float4*)(ip + 4*lane + 128*e);
        float4 r4 = *(const float4*)(rp + 4*lane + 128*e);
        v[e] = make_float4(a.x+r4.x, a.y+r4.y, a.z+r4.z, a.w+r4.w);
        s += v[e].x + v[e].y + v[e].z + v[e].w;
    }
    #pragma unroll
    for (int off = 16; off; off >>= 1) s += __shfl_xor_sync(0xffffffffu, s, off);
    float mean = s * (1.f/512.f);
    float q = 0.f;
    #pragma unroll
    for (int e = 0; e < 4; ++e) {
        float dx = v[e].x-mean, dy = v[e].y-mean, dz = v[e].z-mean, dw = v[e].w-mean;
        q += dx*dx + dy*dy + dz*dz + dw*dw;
    }
    #pragma unroll
    for (int off = 16; off; off >>= 1) q += __shfl_xor_sync(0xffffffffu, q, off);
    float rstd = rsqrtf(q * (1.f/512.f) + 1e-5f);
    const float* gp = gg + (size_t)z*512;
    const float* bp = bb + (size_t)z*512;
    #pragma unroll
    for (int e = 0; e < 4; ++e) {
        float4 g4 = *(const float4*)(gp + 4*lane + 128*e);
        float4 b4 = *(const float4*)(bp + 4*lane + 128*e);
        float4 o;
        o.x = (v[e].x-mean)*rstd*g4.x + b4.x;
        o.y = (v[e].y-mean)*rstd*g4.y + b4.y;
        o.z = (v[e].z-mean)*rstd*g4.z + b4.z;
        o.w = (v[e].w-mean)*rstd*g4.w + b4.w;
        if (outf)
            *(float4*)(outf + (size_t)row*512 + 4*lane + 128*e) = o;
        if (outh) {
            __half2 h0 = __floats2half2_rn(o.x, o.y);
            __half2 h1 = __floats2half2_rn(o.z, o.w);
            *(__half2*)(outh + (size_t)row*512 + 4*lane + 128*e)     = h0;
            *(__half2*)(outh + (size_t)row*512 + 4*lane + 128*e + 2) = h1;
        }
    }
}

/* --------------------------- launch ------------------------------ */
extern "C" void kernel_launch(void* const* d_in, const int* in_sizes, int n_in,
                              void* d_out, int out_size)
{
    const float* x     = (const float*)d_in[0];
    const float* wih   = (const float*)d_in[1];
    const float* whh   = (const float*)d_in[2];
    const float* bih   = (const float*)d_in[3];
    const float* bhh   = (const float*)d_in[4];
    const float* wq    = (const float*)d_in[5];
    const float* wk    = (const float*)d_in[6];
    const float* wv    = (const float*)d_in[7];
    const float* wbeat = (const float*)d_in[8];
    const float* ng    = (const float*)d_in[9];
    const float* nb    = (const float*)d_in[10];
    const float* wmix  = (const float*)d_in[11];
    const float* bng   = (const float*)d_in[12];
    const float* bnb   = (const float*)d_in[13];
    float* out = (float*)d_out;

    float *p_xpe, *p_xp, *p_q, *p_k, *p_v, *p_thr, *p_mix;
    __half *p_xpeh, *p_combh, *p_thrh;
    __half *p_wih, *p_wq, *p_wk, *p_wv, *p_wbt, *p_wmx;
    cudaGetSymbolAddress((void**)&p_xpe,   g_xpe);
    cudaGetSymbolAddress((void**)&p_xpeh,  g_xpe_h);
    cudaGetSymbolAddress((void**)&p_xp,    g_xp);
    cudaGetSymbolAddress((void**)&p_q,     g_q);
    cudaGetSymbolAddress((void**)&p_k,     g_kk);
    cudaGetSymbolAddress((void**)&p_v,     g_v);
    cudaGetSymbolAddress((void**)&p_combh, g_comb_h);
    cudaGetSymbolAddress((void**)&p_thr,   g_thr);
    cudaGetSymbolAddress((void**)&p_thrh,  g_thr_h);
    cudaGetSymbolAddress((void**)&p_mix,   g_mix);
    cudaGetSymbolAddress((void**)&p_wih,   g_wih_h);
    cudaGetSymbolAddress((void**)&p_wq,    g_wq_h);
    cudaGetSymbolAddress((void**)&p_wk,    g_wk_h);
    cudaGetSymbolAddress((void**)&p_wv,    g_wv_h);
    cudaGetSymbolAddress((void**)&p_wbt,   g_wbt_h);
    cudaGetSymbolAddress((void**)&p_wmx,   g_wmx_h);

    cudaFuncSetAttribute(gru_kernel,  cudaFuncAttributeMaxDynamicSharedMemorySize, 228096);
    cudaFuncSetAttribute(gemm_kernel, cudaFuncAttributeMaxDynamicSharedMemorySize, 61440);

    init_kernel<<<64, 256>>>();
    pe_add_kernel<<<(T_*D_)/256, 256>>>(x);

    /* weight converts (fp32 -> fp16) */
    f2h_kernel<<<(4*3*D_*D_/4 + 255)/256, 256>>>(wih,   p_wih, 4*3*D_*D_/4);
    f2h_kernel<<<(4*D_*D_/4   + 255)/256, 256>>>(wq,    p_wq,  4*D_*D_/4);
    f2h_kernel<<<(4*D_*D_/4   + 255)/256, 256>>>(wk,    p_wk,  4*D_*D_/4);
    f2h_kernel<<<(4*D_*D_/4   + 255)/256, 256>>>(wv,    p_wv,  4*D_*D_/4);
    f2h_kernel<<<(4*D_*2*D_/4 + 255)/256, 256>>>(wbeat, p_wbt, 4*D_*2*D_/4);
    f2h_kernel<<<(D_*4*D_/4   + 255)/256, 256>>>(wmix,  p_wmx, D_*4*D_/4);

    // xp = wih @ xpe + bih   (M=8192, N=1536, K=512, z=4)
    gemm_kernel<<<dim3(64,12,4), 256, 61440>>>(p_xpeh, 0, 512, 512,
                                        p_wih, (size_t)1536*512, 512,
                                        bih, 1536,
                                        p_xp, (size_t)M_*1536, 1536);
    // q, k, v  (N=512, K=512, z=4)
    gemm_kernel<<<dim3(64,4,4), 256, 61440>>>(p_xpeh, 0, 512, 512, p_wq, (size_t)512*512, 512,
                                       nullptr, 0, p_q, (size_t)M_*512, 512);
    gemm_kernel<<<dim3(64,4,4), 256, 61440>>>(p_xpeh, 0, 512, 512, p_wk, (size_t)512*512, 512,
                                       nullptr, 0, p_k, (size_t)M_*512, 512);
    gemm_kernel<<<dim3(64,4,4), 256, 61440>>>(p_xpeh, 0, 512, 512, p_wv, (size_t)512*512, 512,
                                       nullptr, 0, p_v, (size_t)M_*512, 512);

    attn_kernel<<<4096, 256>>>();
    gru_kernel<<<32, 256, 228096>>>(whh, bhh);

    // beat = w_beat @ comb   (K=1024) -> g_thr (fp32)
    gemm_kernel<<<dim3(64,4,4), 256, 61440>>>(p_combh, (size_t)M_*1024, 1024, 512,
                                       p_wbt, (size_t)512*1024, 1024,
                                       nullptr, 0, p_thr, (size_t)M_*512, 512);
    // thr = LN(beat + xpe) -> fp16
    ln_kernel<<<4096, 256>>>(p_thr, p_xpe, ng, nb, nullptr, p_thrh, 8192);
    // out0 = w_mix @ merged  (K=2048 over the 4 thr chunks)
    gemm_kernel<<<dim3(64,4,1), 256, 61440>>>(p_thrh, 0, 512, (size_t)M_*512,
                                       p_wmx, 0, 2048,
                                       nullptr, 0, p_mix, 0, 512);
    // out = LN(out0 + xpe) -> fp32
    ln_kernel<<<1024, 256>>>(p_mix, p_xpe, bng, bnb, out, nullptr, 0);
}

// round 11
// speedup vs baseline: 1.5704x; 1.5704x over previous
#include <cuda_runtime.h>
#include <cuda_fp16.h>
#include <math.h>
#include <stdint.h>

#define B_ 4
#define T_ 2048
#define D_ 512
#define M_ (B_*T_)   /* 8192 */

/* ------------ static device scratch (no allocations) ------------ */
__device__ float  g_xpe[(size_t)M_*D_];          // x + PE (fp32, residuals)
__device__ __half g_xpe_h[(size_t)M_*D_];        // fp16 GEMM input
__device__ float  g_xp [(size_t)4*M_*3*D_];      // wih @ xpe + bih
__device__ float  g_q  [(size_t)4*M_*D_];
__device__ float  g_kk [(size_t)4*M_*D_];
__device__ float  g_v  [(size_t)4*M_*D_];
__device__ __half g_comb_h[(size_t)4*M_*2*D_];   // [gru | attn] fp16
__device__ float  g_thr[(size_t)4*M_*D_];        // beat (fp32 GEMM out)
__device__ __half g_thr_h[(size_t)4*M_*D_];      // LN(beat+xpe) fp16
__device__ float  g_mix[(size_t)M_*D_];
/* fp16 weights */
__device__ __half g_wih_h [(size_t)4*3*D_*D_];
__device__ __half g_wq_h  [(size_t)4*D_*D_];
__device__ __half g_wk_h  [(size_t)4*D_*D_];
__device__ __half g_wv_h  [(size_t)4*D_*D_];
__device__ __half g_wbt_h [(size_t)4*D_*2*D_];
__device__ __half g_wmx_h [(size_t)D_*4*D_];
/* hidden-state payloads: (tag<<32 | f32 bits), [2 buf][4 kt][4 b][512 j] */
__device__ __align__(128) unsigned long long g_hp[2*4*4*512];

__device__ __forceinline__ uint32_t packh2(float lo, float hi) {
    uint32_t d; asm("cvt.rn.f16x2.f32 %0, %1, %2;" : "=r"(d) : "f"(hi), "f"(lo));
    return d;
}
__device__ __forceinline__ float fsig(float x) {
    return __fdividef(1.f, 1.f + __expf(-x));
}
__device__ __forceinline__ void cp16(void* s, const void* g) {
    uint32_t a = (uint32_t)__cvta_generic_to_shared(s);
    asm volatile("cp.async.cg.shared.global [%0], [%1], 16;" :: "r"(a), "l"(g));
}
__device__ __forceinline__ void ldv2(const unsigned long long* p,
                                     unsigned long long& a, unsigned long long& b) {
    asm volatile("ld.volatile.global.v2.u64 {%0,%1}, [%2];"
                 : "=l"(a), "=l"(b) : "l"(p) : "memory");
}
__device__ __forceinline__ void strx(unsigned long long* p, unsigned long long v) {
    asm volatile("st.relaxed.gpu.global.b64 [%0], %1;" :: "l"(p), "l"(v) : "memory");
}
#define MMA_F16A(C, A0, A1, A2, A3, B0, B1) \
    asm volatile("mma.sync.aligned.m16n8k16.row.col.f32.f16.f16.f32 " \
        "{%0,%1,%2,%3},{%4,%5,%6,%7},{%8,%9},{%0,%1,%2,%3};" \
        : "+f"((C)[0]), "+f"((C)[1]), "+f"((C)[2]), "+f"((C)[3]) \
        : "r"(A0), "r"(A1), "r"(A2), "r"(A3), "r"(B0), "r"(B1))
#define MMA_F16(C, FR, B0, B1) MMA_F16A(C, (FR).x, (FR).y, (FR).z, (FR).w, B0, B1)

/* ---------------------------- init ------------------------------ */
__global__ void init_kernel() {
    int i = blockIdx.x * 256 + threadIdx.x;
    if (i < 2*4*4*512) g_hp[i] = 0ull;
}

/* -------------------- f32 -> f16 convert ------------------------- */
__global__ void f2h_kernel(const float* __restrict__ in, __half* __restrict__ out, int n4) {
    int i = blockIdx.x * 256 + threadIdx.x;
    if (i < n4) {
        float4 v = ((const float4*)in)[i];
        __half2 h0 = __floats2half2_rn(v.x, v.y);
        __half2 h1 = __floats2half2_rn(v.z, v.w);
        ((__half2*)out)[2*i]   = h0;
        ((__half2*)out)[2*i+1] = h1;
    }
}

/* -------------------- positional encoding ----------------------- */
__global__ void pe_add_kernel(const float* __restrict__ x) {
    int idx = blockIdx.x * 256 + threadIdx.x;   // 0 .. T*D-1
    int t = idx >> 9;
    int d = idx & 511;
    const float kfac = -9.210340371976184f / 512.0f;
    float dv  = expf((float)(d & ~1) * kfac);
    float arg = (float)t * dv;
    float pe  = (d & 1) ? cosf(arg) : sinf(arg);
    int slot = d >> 7;
    int off  = d & 127;
    int c    = 5 + slot;
    float ph = ((float)(t % c) / (float)c) * 6.283185307179586f;
    float tv = (off < 64) ? sinf(ph * (float)(off + 1)) : cosf(ph * (float)(off - 63));
    float tot = 0.5f * pe + 0.5f * tv;
    #pragma unroll
    for (int b = 0; b < B_; ++b) {
        float v = x[(size_t)b*(T_*D_) + idx] + tot;
        g_xpe  [(size_t)b*(T_*D_) + idx] = v;
        g_xpe_h[(size_t)b*(T_*D_) + idx] = __float2half(v);
    }
}

/* --------- fp16 tensor-core NT GEMM, cp.async 3-stage ------------ */
__global__ void __launch_bounds__(256)
gemm_kernel(const __half* __restrict__ A, size_t sAz, size_t sAm, size_t sAchunk,
            const __half* __restrict__ W, size_t sWz, int K,
            const float* __restrict__ bias, size_t sBz,
            float* __restrict__ C, size_t sCz, size_t sCm)
{
    extern __shared__ __half hsm[];
    __half* As0 = hsm;             // [3][128][40]
    __half* Bs0 = hsm + 15360;
#define AS(s,r,k) As0[(s)*5120 + (r)*40 + (k)]
#define BS(s,r,k) Bs0[(s)*5120 + (r)*40 + (k)]
    const int z  = blockIdx.z;
    const int m0 = blockIdx.x * 128;
    const int n0 = blockIdx.y * 128;
    const int tid = threadIdx.x;
    const int hr = tid >> 1;
    const int hc = (tid & 1) * 16;
    const int warp = tid >> 5;
    const int lane = tid & 31;
    const int wm = warp >> 1;
    const int wn = warp & 1;
    const int gid = lane >> 2;
    const int tig = lane & 3;

    const __half* Az = A + (size_t)z * sAz;
    const __half* Wz = W + (size_t)z * sWz;

    float acc[2][8][4];
    #pragma unroll
    for (int mf = 0; mf < 2; ++mf)
        #pragma unroll
        for (int nf = 0; nf < 8; ++nf)
            #pragma unroll
            for (int q = 0; q < 4; ++q) acc[mf][nf][q] = 0.f;

    const int nt = K >> 5;
    {
        const __half* ap = Az + (size_t)(m0 + hr) * sAm + hc;
        cp16(&AS(0,hr,hc), ap); cp16(&AS(0,hr,hc+8), ap + 8);
        const __half* wp = Wz + (size_t)(n0 + hr) * K + hc;
        cp16(&BS(0,hr,hc), wp); cp16(&BS(0,hr,hc+8), wp + 8);
        asm volatile("cp.async.commit_group;");
    }
    if (nt > 1) {
        const __half* ap = Az + (size_t)(m0 + hr) * sAm + 32 + hc;
        cp16(&AS(1,hr,hc), ap); cp16(&AS(1,hr,hc+8), ap + 8);
        const __half* wp = Wz + (size_t)(n0 + hr) * K + 32 + hc;
        cp16(&BS(1,hr,hc), wp); cp16(&BS(1,hr,hc+8), wp + 8);
        asm volatile("cp.async.commit_group;");
    }
    for (int kt = 0; kt < nt; ++kt) {
        if (kt + 1 < nt) asm volatile("cp.async.wait_group 1;");
        else             asm volatile("cp.async.wait_group 0;");
        __syncthreads();
        if (kt + 2 < nt) {
            int j0 = (kt + 2) * 32;
            int ps = (kt + 2) % 3;
            const __half* ap = Az + (size_t)(m0 + hr) * sAm + (size_t)(j0 >> 9) * sAchunk + (j0 & 511) + hc;
            cp16(&AS(ps,hr,hc), ap); cp16(&AS(ps,hr,hc+8), ap + 8);
            const __half* wp = Wz + (size_t)(n0 + hr) * K + j0 + hc;
            cp16(&BS(ps,hr,hc), wp); cp16(&BS(ps,hr,hc+8), wp + 8);
            asm volatile("cp.async.commit_group;");
        }
        const int s = kt % 3;
        #pragma unroll
        for (int ks = 0; ks < 2; ++ks) {
            const int kb = ks * 16;
            uint32_t af[2][4];
            #pragma unroll
            for (int mf = 0; mf < 2; ++mf) {
                int m = wm*32 + mf*16 + gid;
                af[mf][0] = *(const uint32_t*)&AS(s, m,   kb + 2*tig);
                af[mf][1] = *(const uint32_t*)&AS(s, m+8, kb + 2*tig);
                af[mf][2] = *(const uint32_t*)&AS(s, m,   kb + 2*tig + 8);
                af[mf][3] = *(const uint32_t*)&AS(s, m+8, kb + 2*tig + 8);
            }
            #pragma unroll
            for (int nf = 0; nf < 8; ++nf) {
                int n = wn*64 + nf*8 + gid;
                uint32_t b0v = *(const uint32_t*)&BS(s, n, kb + 2*tig);
                uint32_t b1v = *(const uint32_t*)&BS(s, n, kb + 2*tig + 8);
                MMA_F16A(acc[0][nf], af[0][0], af[0][1], af[0][2], af[0][3], b0v, b1v);
                MMA_F16A(acc[1][nf], af[1][0], af[1][1], af[1][2], af[1][3], b0v, b1v);
            }
        }
    }

    float* Cz = C + (size_t)z * sCz;
    #pragma unroll
    for (int mf = 0; mf < 2; ++mf) {
        int r0 = m0 + wm*32 + mf*16 + gid;
        #pragma unroll
        for (int nf = 0; nf < 8; ++nf) {
            int col = n0 + wn*64 + nf*8 + 2*tig;
            float bb0 = 0.f, bb1 = 0.f;
            if (bias) {
                bb0 = bias[(size_t)z*sBz + col];
                bb1 = bias[(size_t)z*sBz + col + 1];
            }
            float2 o0 = make_float2(acc[mf][nf][0] + bb0, acc[mf][nf][1] + bb1);
            float2 o1 = make_float2(acc[mf][nf][2] + bb0, acc[mf][nf][3] + bb1);
            *(float2*)(Cz + (size_t)r0      * sCm + col) = o0;
            *(float2*)(Cz + (size_t)(r0+8)  * sCm + col) = o1;
        }
    }
#undef AS
#undef BS
}

/* ------------------ attention body (device fn) ------------------ */
__device__ void attn_body(int gw, int lane) {
    int t  = gw & (T_ - 1);
    int kb = gw >> 11;
    int b  = kb & 3;
    int kt = kb >> 2;
    int c  = 5 + kt;
    int L  = min(c, t + 1);
    size_t rowbase = (size_t)kt * M_ + (size_t)b * T_;
    const float* qp = g_q + (rowbase + t) * D_;
    float4 qv[4];
    #pragma unroll
    for (int e = 0; e < 4; ++e) qv[e] = *(const float4*)(qp + 4*lane + 128*e);

    float sc[8];
    float smax = -1e30f;
    #pragma unroll
    for (int s0 = 0; s0 < 8; ++s0) {
        if (s0 < L) {
            const float* kp = g_kk + (rowbase + t - s0) * D_;
            float a = 0.f;
            #pragma unroll
            for (int e = 0; e < 4; ++e) {
                float4 kv = *(const float4*)(kp + 4*lane + 128*e);
                a += qv[e].x*kv.x + qv[e].y*kv.y + qv[e].z*kv.z + qv[e].w*kv.w;
            }
            #pragma unroll
            for (int off = 16; off; off >>= 1) a += __shfl_xor_sync(0xffffffffu, a, off);
            a *= 0.044194173824159216f;
            sc[s0] = a;
            smax = fmaxf(smax, a);
        }
    }
    float denom = 0.f;
    float4 acc[4];
    #pragma unroll
    for (int e = 0; e < 4; ++e) acc[e] = make_float4(0.f, 0.f, 0.f, 0.f);
    #pragma unroll
    for (int s0 = 0; s0 < 8; ++s0) {
        if (s0 < L) {
            float p = expf(sc[s0] - smax);
            denom += p;
            const float* vp = g_v + (rowbase + t - s0) * D_;
            #pragma unroll
            for (int e = 0; e < 4; ++e) {
                float4 vv = *(const float4*)(vp + 4*lane + 128*e);
                acc[e].x += p*vv.x; acc[e].y += p*vv.y;
                acc[e].z += p*vv.z; acc[e].w += p*vv.w;
            }
        }
    }
    float inv = 1.f / denom;
    __half* op = g_comb_h + (rowbase + t) * 1024 + 512;
    #pragma unroll
    for (int e = 0; e < 4; ++e) {
        __half2 h0 = __floats2half2_rn(acc[e].x*inv, acc[e].y*inv);
        __half2 h1 = __floats2half2_rn(acc[e].z*inv, acc[e].w*inv);
        *(__half2*)(op + 4*lane + 128*e)     = h0;
        *(__half2*)(op + 4*lane + 128*e + 2) = h1;
    }
}

/* ------------------- fat kernel: GRU + attn ----------------------
   CTAs 0..127 : GRU (R9 structure: blockIdx = kt*32 + c, CTA owns
                 16 hidden units, fp16 mma, payload handoff)
   CTAs 128..147: attention helpers, grid-stride over 4096 jobs.
   1 CTA/SM (122880B smem) -> all 148 co-resident in one wave.      */
__global__ void __launch_bounds__(256, 1)
gru_kernel(const float* __restrict__ whh, const float* __restrict__ bhh)
{
    extern __shared__ float sm[];
    const int tid  = threadIdx.x;
    const int lane = tid & 31;
    const int w    = tid >> 5;

    if (blockIdx.x >= 128) {                 /* ---- attn helpers ---- */
        int helper = blockIdx.x - 128;       /* 0..19 */
        for (int job = helper; job < 4096; job += 20)
            attn_body(job * 8 + w, lane);
        return;
    }

    uint4* sAf  = (uint4*)sm;          // 3072 x 16B = 49152B
    float* sRed = sm + 12288;          // [2][48 rows][4 b][8 warps]
    float* sBhh = sm + 12288 + 3072;   // 48

    const int kt   = blockIdx.x >> 5;
    const int c    = blockIdx.x & 31;
    const int gid  = lane >> 2;
    const int tig  = lane & 3;

    /* ---- one-time: build fp16 A fragments from whh ---- */
    const float* wkp = whh + (size_t)kt * (1536*512);
    for (int e = tid; e < 3072; e += 256) {
        int el = e & 31;
        int g  = (e >> 5) % 3;
        int ks = e / 96;
        int eg = el >> 2, et = el & 3;
        const float* w0 = wkp + (size_t)(g*512 + c*16 + eg) * 512;
        const float* w1 = w0 + 8*512;
        int k0 = ks*16 + 2*et;
        float2 p0 = *(const float2*)(w0 + k0);
        float2 p1 = *(const float2*)(w1 + k0);
        float2 p2 = *(const float2*)(w0 + k0 + 8);
        float2 p3 = *(const float2*)(w1 + k0 + 8);
        uint4 fr;
        fr.x = packh2(p0.x, p0.y);
        fr.y = packh2(p1.x, p1.y);
        fr.z = packh2(p2.x, p2.y);
        fr.w = packh2(p3.x, p3.y);
        sAf[e] = fr;
    }
    if (tid < 48) {
        int g = tid >> 4, u2 = tid & 15;
        sBhh[tid] = bhh[kt*1536 + g*512 + c*16 + u2];
    }
    __syncthreads();

    const int u  = tid & 15;
    const int b4 = tid >> 4;
    const int need = (gid < 4);
    float hold = 0.f;

    /* xp pipeline: preload step 0 */
    float xr = 0.f, xz = 0.f, xn = 0.f;
    if (tid < 64) {
        const float* xp0 = g_xp + ((size_t)(kt*M_ + b4*T_))*1536 + c*16 + u;
        xr = __ldg(xp0); xz = __ldg(xp0 + 512); xn = __ldg(xp0 + 1024);
    }

    for (int t = 0; t < T_; ++t) {
        /* poll the 16 payloads this lane consumes (4 producer CTAs) */
        unsigned long long pl[4][4];
        #pragma unroll
        for (int i = 0; i < 4; ++i)
            #pragma unroll
            for (int q = 0; q < 4; ++q) pl[i][q] = 0ull;
        {
            const unsigned long long* hb =
                g_hp + ((size_t)(t & 1) * 4 + kt) * 2048 + (size_t)gid * 512;
            const uint32_t tag = (uint32_t)t;
            for (;;) {
                int ok = 1;
                if (need) {
                    #pragma unroll
                    for (int i = 0; i < 4; ++i) {
                        int k0 = ((w << 2) + i) * 16 + 2 * tig;
                        ldv2(hb + k0,     pl[i][0], pl[i][1]);
                        ldv2(hb + k0 + 8, pl[i][2], pl[i][3]);
                        #pragma unroll
                        for (int q = 0; q < 4; ++q)
                            ok &= ((uint32_t)(pl[i][q] >> 32) == tag);
                    }
                }
                if (__all_sync(0xffffffffu, ok)) break;
            }
        }
        /* consume this step's pipelined xp, issue next step's loads */
        float xr_c = xr, xz_c = xz, xn_c = xn;
        if (tid < 64 && t + 1 < T_) {
            const float* xp = g_xp + ((size_t)(kt*M_ + b4*T_ + t + 1))*1536 + c*16 + u;
            xr = __ldg(xp); xz = __ldg(xp + 512); xn = __ldg(xp + 1024);
        }
        /* fragments + MMAs */
        float acc[3][4];
        #pragma unroll
        for (int g = 0; g < 3; ++g)
            #pragma unroll
            for (int q = 0; q < 4; ++q) acc[g][q] = 0.f;
        #pragma unroll
        for (int i = 0; i < 4; ++i) {
            uint32_t b0 = packh2(__uint_as_float((uint32_t)pl[i][0]),
                                 __uint_as_float((uint32_t)pl[i][1]));
            uint32_t b1 = packh2(__uint_as_float((uint32_t)pl[i][2]),
                                 __uint_as_float((uint32_t)pl[i][3]));
            int ks = (w << 2) + i;
            #pragma unroll
            for (int g = 0; g < 3; ++g) {
                uint4 fr = sAf[(ks*3 + g)*32 + lane];
                MMA_F16(acc[g], fr, b0, b1);
            }
        }
        /* store partials (lanes with real batches: tig<2), parity buffer */
        float* red = sRed + (t & 1) * 1536;
        if (tig < 2) {
            #pragma unroll
            for (int g = 0; g < 3; ++g) {
                int r0 = (g*16 + gid)*4 + 2*tig;
                int r1 = (g*16 + gid + 8)*4 + 2*tig;
                red[(r0  )*8 + w] = acc[g][0];
                red[(r0+1)*8 + w] = acc[g][1];
                red[(r1  )*8 + w] = acc[g][2];
                red[(r1+1)*8 + w] = acc[g][3];
            }
        }
        __syncthreads();

        /* gates + state update (64 threads: tid = b4*16 + u) */
        if (tid < 64) {
            const float* pr = red + ((u)*4    + b4)*8;
            const float* pz = red + ((16+u)*4 + b4)*8;
            const float* pn = red + ((32+u)*4 + b4)*8;
            float4 r0 = *(const float4*)pr, r1 = *(const float4*)(pr+4);
            float4 z0 = *(const float4*)pz, z1 = *(const float4*)(pz+4);
            float4 n0 = *(const float4*)pn, n1 = *(const float4*)(pn+4);
            float hr = r0.x+r0.y+r0.z+r0.w + r1.x+r1.y+r1.z+r1.w + sBhh[u];
            float hz = z0.x+z0.y+z0.z+z0.w + z1.x+z1.y+z1.z+z1.w + sBhh[16+u];
            float hn = n0.x+n0.y+n0.z+n0.w + n1.x+n1.y+n1.z+n1.w + sBhh[32+u];
            float r = fsig(xr_c + hr);
            float z = fsig(xz_c + hz);
            float ax = xn_c + r * hn;
            float n = 1.f - __fdividef(2.f, __expf(2.f*ax) + 1.f);
            float hnew = (1.f - z) * n + z * hold;
            hold = hnew;
            unsigned long long pay =
                ((unsigned long long)(uint32_t)(t + 1) << 32) |
                (unsigned long long)__float_as_uint(hnew);
            strx(g_hp + ((size_t)((t + 1) & 1) * 4 + kt) * 2048 +
                 (size_t)b4 * 512 + c*16 + u, pay);
            g_comb_h[((size_t)(kt*M_ + b4*T_ + t)) * 1024 + c*16 + u] = __float2half(hnew);
        }
    }
}

/* ----------------- layernorm (+residual) ------------------------ */
__global__ void ln_kernel(const float* __restrict__ inp, const float* __restrict__ res,
                          const float* __restrict__ gg, const float* __restrict__ bb,
                          float* __restrict__ outf, __half* __restrict__ outh, int zdiv)
{
    int row  = blockIdx.x * 8 + (threadIdx.x >> 5);
    int lane = threadIdx.x & 31;
    int z    = zdiv ? (row / zdiv) : 0;
    int rrow = zdiv ? (row % zdiv) : row;
    const float* ip = inp + (size_t)row * 512;
    const float* rp = res + (size_t)rrow * 512;
    float4 v[4];
    float s = 0.f;
    #pragma unroll
    for (int e = 0; e < 4; ++e) {
        float4 a  = *(const float4*)(ip + 4*lane + 128*e);
        float4 r4 = *(const float4*)(rp + 4*lane + 128*e);
        v[e] = make_float4(a.x+r4.x, a.y+r4.y, a.z+r4.z, a.w+r4.w);
        s += v[e].x + v[e].y + v[e].z + v[e].w;
    }
    #pragma unroll
    for (int off = 16; off; off >>= 1) s += __shfl_xor_sync(0xffffffffu, s, off);
    float mean = s * (1.f/512.f);
    float q = 0.f;
    #pragma unroll
    for (int e = 0; e < 4; ++e) {
        float dx = v[e].x-mean, dy = v[e].y-mean, dz = v[e].z-mean, dw = v[e].w-mean;
        q += dx*dx + dy*dy + dz*dz + dw*dw;
    }
    #pragma unroll
    for (int off = 16; off; off >>= 1) q += __shfl_xor_sync(0xffffffffu, q, off);
    float rstd = rsqrtf(q * (1.f/512.f) + 1e-5f);
    const float* gp = gg + (size_t)z*512;
    const float* bp = bb + (size_t)z*512;
    #pragma unroll
    for (int e = 0; e < 4; ++e) {
        float4 g4 = *(const float4*)(gp + 4*lane + 128*e);
        float4 b4 = *(const float4*)(bp + 4*lane + 128*e);
        float4 o;
        o.x = (v[e].x-mean)*rstd*g4.x + b4.x;
        o.y = (v[e].y-mean)*rstd*g4.y + b4.y;
        o.z = (v[e].z-mean)*rstd*g4.z + b4.z;
        o.w = (v[e].w-mean)*rstd*g4.w + b4.w;
        if (outf)
            *(float4*)(outf + (size_t)row*512 + 4*lane + 128*e) = o;
        if (outh) {
            __half2 h0 = __floats2half2_rn(o.x, o.y);
            __half2 h1 = __floats2half2_rn(o.z, o.w);
            *(__half2*)(outh + (size_t)row*512 + 4*lane + 128*e)     = h0;
            *(__half2*)(outh + (size_t)row*512 + 4*lane + 128*e + 2) = h1;
        }
    }
}

/* --------------------------- launch ------------------------------ */
extern "C" void kernel_launch(void* const* d_in, const int* in_sizes, int n_in,
                              void* d_out, int out_size)
{
    const float* x     = (const float*)d_in[0];
    const float* wih   = (const float*)d_in[1];
    const float* whh   = (const float*)d_in[2];
    const float* bih   = (const float*)d_in[3];
    const float* bhh   = (const float*)d_in[4];
    const float* wq    = (const float*)d_in[5];
    const float* wk    = (const float*)d_in[6];
    const float* wv    = (const float*)d_in[7];
    const float* wbeat = (const float*)d_in[8];
    const float* ng    = (const float*)d_in[9];
    const float* nb    = (const float*)d_in[10];
    const float* wmix  = (const float*)d_in[11];
    const float* bng   = (const float*)d_in[12];
    const float* bnb   = (const float*)d_in[13];
    float* out = (float*)d_out;

    float *p_xpe, *p_xp, *p_q, *p_k, *p_v, *p_thr, *p_mix;
    __half *p_xpeh, *p_combh, *p_thrh;
    __half *p_wih, *p_wq, *p_wk, *p_wv, *p_wbt, *p_wmx;
    cudaGetSymbolAddress((void**)&p_xpe,   g_xpe);
    cudaGetSymbolAddress((void**)&p_xpeh,  g_xpe_h);
    cudaGetSymbolAddress((void**)&p_xp,    g_xp);
    cudaGetSymbolAddress((void**)&p_q,     g_q);
    cudaGetSymbolAddress((void**)&p_k,     g_kk);
    cudaGetSymbolAddress((void**)&p_v,     g_v);
    cudaGetSymbolAddress((void**)&p_combh, g_comb_h);
    cudaGetSymbolAddress((void**)&p_thr,   g_thr);
    cudaGetSymbolAddress((void**)&p_thrh,  g_thr_h);
    cudaGetSymbolAddress((void**)&p_mix,   g_mix);
    cudaGetSymbolAddress((void**)&p_wih,   g_wih_h);
    cudaGetSymbolAddress((void**)&p_wq,    g_wq_h);
    cudaGetSymbolAddress((void**)&p_wk,    g_wk_h);
    cudaGetSymbolAddress((void**)&p_wv,    g_wv_h);
    cudaGetSymbolAddress((void**)&p_wbt,   g_wbt_h);
    cudaGetSymbolAddress((void**)&p_wmx,   g_wmx_h);

    cudaFuncSetAttribute(gru_kernel,  cudaFuncAttributeMaxDynamicSharedMemorySize, 122880);
    cudaFuncSetAttribute(gemm_kernel, cudaFuncAttributeMaxDynamicSharedMemorySize, 61440);

    init_kernel<<<64, 256>>>();
    pe_add_kernel<<<(T_*D_)/256, 256>>>(x);

    /* weight converts (fp32 -> fp16) */
    f2h_kernel<<<(4*3*D_*D_/4 + 255)/256, 256>>>(wih,   p_wih, 4*3*D_*D_/4);
    f2h_kernel<<<(4*D_*D_/4   + 255)/256, 256>>>(wq,    p_wq,  4*D_*D_/4);
    f2h_kernel<<<(4*D_*D_/4   + 255)/256, 256>>>(wk,    p_wk,  4*D_*D_/4);
    f2h_kernel<<<(4*D_*D_/4   + 255)/256, 256>>>(wv,    p_wv,  4*D_*D_/4);
    f2h_kernel<<<(4*D_*2*D_/4 + 255)/256, 256>>>(wbeat, p_wbt, 4*D_*2*D_/4);
    f2h_kernel<<<(D_*4*D_/4   + 255)/256, 256>>>(wmix,  p_wmx, D_*4*D_/4);

    // xp = wih @ xpe + bih   (M=8192, N=1536, K=512, z=4)
    gemm_kernel<<<dim3(64,12,4), 256, 61440>>>(p_xpeh, 0, 512, 512,
                                        p_wih, (size_t)1536*512, 512,
                                        bih, 1536,
                                        p_xp, (size_t)M_*1536, 1536);
    // q, k, v  (N=512, K=512, z=4)
    gemm_kernel<<<dim3(64,4,4), 256, 61440>>>(p_xpeh, 0, 512, 512, p_wq, (size_t)512*512, 512,
                                       nullptr, 0, p_q, (size_t)M_*512, 512);
    gemm_kernel<<<dim3(64,4,4), 256, 61440>>>(p_xpeh, 0, 512, 512, p_wk, (size_t)512*512, 512,
                                       nullptr, 0, p_k, (size_t)M_*512, 512);
    gemm_kernel<<<dim3(64,4,4), 256, 61440>>>(p_xpeh, 0, 512, 512, p_wv, (size_t)512*512, 512,
                                       nullptr, 0, p_v, (size_t)M_*512, 512);

    /* fat kernel: 128 GRU CTAs + 20 attention helper CTAs */
    gru_kernel<<<148, 256, 122880>>>(whh, bhh);

    // beat = w_beat @ comb   (K=1024) -> g_thr (fp32)
    gemm_kernel<<<dim3(64,4,4), 256, 61440>>>(p_combh, (size_t)M_*1024, 1024, 512,
                                       p_wbt, (size_t)512*1024, 1024,
                                       nullptr, 0, p_thr, (size_t)M_*512, 512);
    // thr = LN(beat + xpe) -> fp16
    ln_kernel<<<4096, 256>>>(p_thr, p_xpe, ng, nb, nullptr, p_thrh, 8192);
    // out0 = w_mix @ merged  (K=2048 over the 4 thr chunks)
    gemm_kernel<<<dim3(64,4,1), 256, 61440>>>(p_thrh, 0, 512, (size_t)M_*512,
                                       p_wmx, 0, 2048,
                                       nullptr, 0, p_mix, 0, 512);
    // out = LN(out0 + xpe) -> fp32
    ln_kernel<<<1024, 256>>>(p_mix, p_xpe, bng, bnb, out, nullptr, 0);
}

// round 12
// speedup vs baseline: 1.5944x; 1.0152x over previous
#include <cuda_runtime.h>
#include <cuda_fp16.h>
#include <math.h>
#include <stdint.h>

#define B_ 4
#define T_ 2048
#define D_ 512
#define M_ (B_*T_)   /* 8192 */

/* ------------ static device scratch (no allocations) ------------ */
__device__ float  g_xpe[(size_t)M_*D_];          // x + PE (fp32, residuals)
__device__ __half g_xpe_h[(size_t)M_*D_];        // fp16 GEMM input
__device__ float  g_xp [(size_t)4*M_*3*D_];      // wih @ xpe + bih
__device__ float  g_q  [(size_t)4*M_*D_];
__device__ float  g_kk [(size_t)4*M_*D_];
__device__ float  g_v  [(size_t)4*M_*D_];
__device__ __half g_comb_h[(size_t)4*M_*2*D_];   // [gru | attn] fp16
__device__ float  g_thr[(size_t)4*M_*D_];        // beat (fp32 GEMM out)
__device__ __half g_thr_h[(size_t)4*M_*D_];      // LN(beat+xpe) fp16
__device__ float  g_mix[(size_t)M_*D_];
/* fp16 weights */
__device__ __half g_wih_h [(size_t)4*3*D_*D_];
__device__ __half g_wq_h  [(size_t)4*D_*D_];
__device__ __half g_wk_h  [(size_t)4*D_*D_];
__device__ __half g_wv_h  [(size_t)4*D_*D_];
__device__ __half g_wbt_h [(size_t)4*D_*2*D_];
__device__ __half g_wmx_h [(size_t)D_*4*D_];
/* hidden-state payloads: (tag<<32 | f32 bits), [2 buf][4 kt][4 b][512 j] */
__device__ __align__(128) unsigned long long g_hp[2*4*4*512];
__device__ int g_hctr;                           // helper qkv-done counter

__device__ __forceinline__ uint32_t packh2(float lo, float hi) {
    uint32_t d; asm("cvt.rn.f16x2.f32 %0, %1, %2;" : "=r"(d) : "f"(hi), "f"(lo));
    return d;
}
__device__ __forceinline__ float fsig(float x) {
    return __fdividef(1.f, 1.f + __expf(-x));
}
__device__ __forceinline__ void cp16(void* s, const void* g) {
    uint32_t a = (uint32_t)__cvta_generic_to_shared(s);
    asm volatile("cp.async.cg.shared.global [%0], [%1], 16;" :: "r"(a), "l"(g));
}
__device__ __forceinline__ void ldv2(const unsigned long long* p,
                                     unsigned long long& a, unsigned long long& b) {
    asm volatile("ld.volatile.global.v2.u64 {%0,%1}, [%2];"
                 : "=l"(a), "=l"(b) : "l"(p) : "memory");
}
__device__ __forceinline__ void strx(unsigned long long* p, unsigned long long v) {
    asm volatile("st.relaxed.gpu.global.b64 [%0], %1;" :: "l"(p), "l"(v) : "memory");
}
__device__ __forceinline__ int ldacq(const int* p) {
    int v; asm volatile("ld.acquire.gpu.global.b32 %0, [%1];" : "=r"(v) : "l"(p) : "memory");
    return v;
}
#define MMA_F16A(C, A0, A1, A2, A3, B0, B1) \
    asm volatile("mma.sync.aligned.m16n8k16.row.col.f32.f16.f16.f32 " \
        "{%0,%1,%2,%3},{%4,%5,%6,%7},{%8,%9},{%0,%1,%2,%3};" \
        : "+f"((C)[0]), "+f"((C)[1]), "+f"((C)[2]), "+f"((C)[3]) \
        : "r"(A0), "r"(A1), "r"(A2), "r"(A3), "r"(B0), "r"(B1))
#define MMA_F16(C, FR, B0, B1) MMA_F16A(C, (FR).x, (FR).y, (FR).z, (FR).w, B0, B1)

/* ---------------------------- init ------------------------------ */
__global__ void init_kernel() {
    int i = blockIdx.x * 256 + threadIdx.x;
    if (i < 2*4*4*512) g_hp[i] = 0ull;
    if (i == 0) g_hctr = 0;
}

/* -------------------- f32 -> f16 convert ------------------------- */
__global__ void f2h_kernel(const float* __restrict__ in, __half* __restrict__ out, int n4) {
    int i = blockIdx.x * 256 + threadIdx.x;
    if (i < n4) {
        float4 v = ((const float4*)in)[i];
        __half2 h0 = __floats2half2_rn(v.x, v.y);
        __half2 h1 = __floats2half2_rn(v.z, v.w);
        ((__half2*)out)[2*i]   = h0;
        ((__half2*)out)[2*i+1] = h1;
    }
}

/* -------------------- positional encoding ----------------------- */
__global__ void pe_add_kernel(const float* __restrict__ x) {
    int idx = blockIdx.x * 256 + threadIdx.x;   // 0 .. T*D-1
    int t = idx >> 9;
    int d = idx & 511;
    const float kfac = -9.210340371976184f / 512.0f;
    float dv  = expf((float)(d & ~1) * kfac);
    float arg = (float)t * dv;
    float pe  = (d & 1) ? cosf(arg) : sinf(arg);
    int slot = d >> 7;
    int off  = d & 127;
    int c    = 5 + slot;
    float ph = ((float)(t % c) / (float)c) * 6.283185307179586f;
    float tv = (off < 64) ? sinf(ph * (float)(off + 1)) : cosf(ph * (float)(off - 63));
    float tot = 0.5f * pe + 0.5f * tv;
    #pragma unroll
    for (int b = 0; b < B_; ++b) {
        float v = x[(size_t)b*(T_*D_) + idx] + tot;
        g_xpe  [(size_t)b*(T_*D_) + idx] = v;
        g_xpe_h[(size_t)b*(T_*D_) + idx] = __float2half(v);
    }
}

/* --------- fp16 tensor-core NT GEMM body, cp.async 3-stage -------
   C[m,n] += A(m,j)*W[n*K+j] (+bias[n]); tiles [row][40-half pitch]. */
__device__ void gemm_body(const __half* __restrict__ Az, size_t sAm, size_t sAchunk,
                          const __half* __restrict__ Wz, int K,
                          const float* __restrict__ biasz,
                          float* __restrict__ Cz, size_t sCm,
                          int m0, int n0, __half* hsm, int tid)
{
    __half* As0 = hsm;             // [3][128][40]
    __half* Bs0 = hsm + 15360;
#define AS(s,r,k) As0[(s)*5120 + (r)*40 + (k)]
#define BS(s,r,k) Bs0[(s)*5120 + (r)*40 + (k)]
    const int hr = tid >> 1;
    const int hc = (tid & 1) * 16;
    const int warp = tid >> 5;
    const int lane = tid & 31;
    const int wm = warp >> 1;
    const int wn = warp & 1;
    const int gid = lane >> 2;
    const int tig = lane & 3;

    float acc[2][8][4];
    #pragma unroll
    for (int mf = 0; mf < 2; ++mf)
        #pragma unroll
        for (int nf = 0; nf < 8; ++nf)
            #pragma unroll
            for (int q = 0; q < 4; ++q) acc[mf][nf][q] = 0.f;

    const int nt = K >> 5;
    {
        const __half* ap = Az + (size_t)(m0 + hr) * sAm + hc;
        cp16(&AS(0,hr,hc), ap); cp16(&AS(0,hr,hc+8), ap + 8);
        const __half* wp = Wz + (size_t)(n0 + hr) * K + hc;
        cp16(&BS(0,hr,hc), wp); cp16(&BS(0,hr,hc+8), wp + 8);
        asm volatile("cp.async.commit_group;");
    }
    if (nt > 1) {
        const __half* ap = Az + (size_t)(m0 + hr) * sAm + 32 + hc;
        cp16(&AS(1,hr,hc), ap); cp16(&AS(1,hr,hc+8), ap + 8);
        const __half* wp = Wz + (size_t)(n0 + hr) * K + 32 + hc;
        cp16(&BS(1,hr,hc), wp); cp16(&BS(1,hr,hc+8), wp + 8);
        asm volatile("cp.async.commit_group;");
    }
    for (int kt = 0; kt < nt; ++kt) {
        if (kt + 1 < nt) asm volatile("cp.async.wait_group 1;");
        else             asm volatile("cp.async.wait_group 0;");
        __syncthreads();
        if (kt + 2 < nt) {
            int j0 = (kt + 2) * 32;
            int ps = (kt + 2) % 3;
            const __half* ap = Az + (size_t)(m0 + hr) * sAm + (size_t)(j0 >> 9) * sAchunk + (j0 & 511) + hc;
            cp16(&AS(ps,hr,hc), ap); cp16(&AS(ps,hr,hc+8), ap + 8);
            const __half* wp = Wz + (size_t)(n0 + hr) * K + j0 + hc;
            cp16(&BS(ps,hr,hc), wp); cp16(&BS(ps,hr,hc+8), wp + 8);
            asm volatile("cp.async.commit_group;");
        }
        const int s = kt % 3;
        #pragma unroll
        for (int ks = 0; ks < 2; ++ks) {
            const int kb = ks * 16;
            uint32_t af[2][4];
            #pragma unroll
            for (int mf = 0; mf < 2; ++mf) {
                int m = wm*32 + mf*16 + gid;
                af[mf][0] = *(const uint32_t*)&AS(s, m,   kb + 2*tig);
                af[mf][1] = *(const uint32_t*)&AS(s, m+8, kb + 2*tig);
                af[mf][2] = *(const uint32_t*)&AS(s, m,   kb + 2*tig + 8);
                af[mf][3] = *(const uint32_t*)&AS(s, m+8, kb + 2*tig + 8);
            }
            #pragma unroll
            for (int nf = 0; nf < 8; ++nf) {
                int n = wn*64 + nf*8 + gid;
                uint32_t b0v = *(const uint32_t*)&BS(s, n, kb + 2*tig);
                uint32_t b1v = *(const uint32_t*)&BS(s, n, kb + 2*tig + 8);
                MMA_F16A(acc[0][nf], af[0][0], af[0][1], af[0][2], af[0][3], b0v, b1v);
                MMA_F16A(acc[1][nf], af[1][0], af[1][1], af[1][2], af[1][3], b0v, b1v);
            }
        }
    }

    #pragma unroll
    for (int mf = 0; mf < 2; ++mf) {
        int r0 = m0 + wm*32 + mf*16 + gid;
        #pragma unroll
        for (int nf = 0; nf < 8; ++nf) {
            int col = n0 + wn*64 + nf*8 + 2*tig;
            float bb0 = 0.f, bb1 = 0.f;
            if (biasz) {
                bb0 = biasz[col];
                bb1 = biasz[col + 1];
            }
            float2 o0 = make_float2(acc[mf][nf][0] + bb0, acc[mf][nf][1] + bb1);
            float2 o1 = make_float2(acc[mf][nf][2] + bb0, acc[mf][nf][3] + bb1);
            *(float2*)(Cz + (size_t)r0      * sCm + col) = o0;
            *(float2*)(Cz + (size_t)(r0+8)  * sCm + col) = o1;
        }
    }
#undef AS
#undef BS
}

__global__ void __launch_bounds__(256)
gemm_kernel(const __half* __restrict__ A, size_t sAz, size_t sAm, size_t sAchunk,
            const __half* __restrict__ W, size_t sWz, int K,
            const float* __restrict__ bias, size_t sBz,
            float* __restrict__ C, size_t sCz, size_t sCm)
{
    extern __shared__ __half hsm[];
    const int z = blockIdx.z;
    gemm_body(A + (size_t)z * sAz, sAm, sAchunk,
              W + (size_t)z * sWz, K,
              bias ? bias + (size_t)z * sBz : nullptr,
              C + (size_t)z * sCz, sCm,
              blockIdx.x * 128, blockIdx.y * 128, hsm, threadIdx.x);
}

/* ------------------ attention body (device fn) ------------------ */
__device__ void attn_body(int gw, int lane) {
    int t  = gw & (T_ - 1);
    int kb = gw >> 11;
    int b  = kb & 3;
    int kt = kb >> 2;
    int c  = 5 + kt;
    int L  = min(c, t + 1);
    size_t rowbase = (size_t)kt * M_ + (size_t)b * T_;
    const float* qp = g_q + (rowbase + t) * D_;
    float4 qv[4];
    #pragma unroll
    for (int e = 0; e < 4; ++e) qv[e] = *(const float4*)(qp + 4*lane + 128*e);

    float sc[8];
    float smax = -1e30f;
    #pragma unroll
    for (int s0 = 0; s0 < 8; ++s0) {
        if (s0 < L) {
            const float* kp = g_kk + (rowbase + t - s0) * D_;
            float a = 0.f;
            #pragma unroll
            for (int e = 0; e < 4; ++e) {
                float4 kv = *(const float4*)(kp + 4*lane + 128*e);
                a += qv[e].x*kv.x + qv[e].y*kv.y + qv[e].z*kv.z + qv[e].w*kv.w;
            }
            #pragma unroll
            for (int off = 16; off; off >>= 1) a += __shfl_xor_sync(0xffffffffu, a, off);
            a *= 0.044194173824159216f;
            sc[s0] = a;
            smax = fmaxf(smax, a);
        }
    }
    float denom = 0.f;
    float4 acc[4];
    #pragma unroll
    for (int e = 0; e < 4; ++e) acc[e] = make_float4(0.f, 0.f, 0.f, 0.f);
    #pragma unroll
    for (int s0 = 0; s0 < 8; ++s0) {
        if (s0 < L) {
            float p = expf(sc[s0] - smax);
            denom += p;
            const float* vp = g_v + (rowbase + t - s0) * D_;
            #pragma unroll
            for (int e = 0; e < 4; ++e) {
                float4 vv = *(const float4*)(vp + 4*lane + 128*e);
                acc[e].x += p*vv.x; acc[e].y += p*vv.y;
                acc[e].z += p*vv.z; acc[e].w += p*vv.w;
            }
        }
    }
    float inv = 1.f / denom;
    __half* op = g_comb_h + (rowbase + t) * 1024 + 512;
    #pragma unroll
    for (int e = 0; e < 4; ++e) {
        __half2 h0 = __floats2half2_rn(acc[e].x*inv, acc[e].y*inv);
        __half2 h1 = __floats2half2_rn(acc[e].z*inv, acc[e].w*inv);
        *(__half2*)(op + 4*lane + 128*e)     = h0;
        *(__half2*)(op + 4*lane + 128*e + 2) = h1;
    }
}

/* ------------------- fat kernel: GRU + qkv + attn ----------------
   CTAs 0..127 : GRU (blockIdx = kt*32 + c, CTA owns 16 hidden units,
                 fp16 mma, payload handoff, split barrier).
   CTAs 128..147: helpers — qkv GEMM tiles (3072), counter barrier,
                 then attention (4096 jobs).                        */
__global__ void __launch_bounds__(256, 1)
gru_kernel(const float* __restrict__ whh, const float* __restrict__ bhh)
{
    extern __shared__ float sm[];
    const int tid  = threadIdx.x;
    const int lane = tid & 31;
    const int w    = tid >> 5;

    if (blockIdx.x >= 128) {                 /* ---- helpers ---- */
        int helper = blockIdx.x - 128;       /* 0..19 */
        __half* hsm = (__half*)sm;
        /* qkv: 3 gemms x (64 m x 4 n x 4 z) = 3072 tiles */
        for (int job = helper; job < 3072; job += 20) {
            int which = job / 1024;
            int rem   = job & 1023;
            int z     = rem >> 8;
            int mn    = rem & 255;
            const __half* Wsel = (which == 0) ? g_wq_h : (which == 1) ? g_wk_h : g_wv_h;
            float*        Csel = (which == 0) ? g_q    : (which == 1) ? g_kk   : g_v;
            gemm_body(g_xpe_h, 512, 0,
                      Wsel + (size_t)z*512*512, 512, nullptr,
                      Csel + (size_t)z*M_*512, 512,
                      (mn >> 2) * 128, (mn & 3) * 128, hsm, tid);
            __syncthreads();
        }
        /* publish qkv, wait for all 20 helpers */
        __threadfence();
        __syncthreads();
        if (tid == 0) {
            atomicAdd(&g_hctr, 1);
            while (ldacq(&g_hctr) < 20) { }
        }
        __syncthreads();
        for (int job = helper; job < 4096; job += 20)
            attn_body(job * 8 + w, lane);
        return;
    }

    uint4* sAf  = (uint4*)sm;          // 3072 x 16B = 49152B
    float* sRed = sm + 12288;          // [2][48 rows][4 b][8 warps]
    float* sBhh = sm + 12288 + 3072;   // 48

    const int kt   = blockIdx.x >> 5;
    const int c    = blockIdx.x & 31;
    const int gid  = lane >> 2;
    const int tig  = lane & 3;

    /* ---- one-time: build fp16 A fragments from whh ---- */
    const float* wkp = whh + (size_t)kt * (1536*512);
    for (int e = tid; e < 3072; e += 256) {
        int el = e & 31;
        int g  = (e >> 5) % 3;
        int ks = e / 96;
        int eg = el >> 2, et = el & 3;
        const float* w0 = wkp + (size_t)(g*512 + c*16 + eg) * 512;
        const float* w1 = w0 + 8*512;
        int k0 = ks*16 + 2*et;
        float2 p0 = *(const float2*)(w0 + k0);
        float2 p1 = *(const float2*)(w1 + k0);
        float2 p2 = *(const float2*)(w0 + k0 + 8);
        float2 p3 = *(const float2*)(w1 + k0 + 8);
        uint4 fr;
        fr.x = packh2(p0.x, p0.y);
        fr.y = packh2(p1.x, p1.y);
        fr.z = packh2(p2.x, p2.y);
        fr.w = packh2(p3.x, p3.y);
        sAf[e] = fr;
    }
    if (tid < 48) {
        int g = tid >> 4, u2 = tid & 15;
        sBhh[tid] = bhh[kt*1536 + g*512 + c*16 + u2];
    }
    __syncthreads();

    const int u  = tid & 15;
    const int b4 = tid >> 4;
    const int need = (gid < 4);
    float hold = 0.f;

    /* xp pipeline: preload step 0 */
    float xr = 0.f, xz = 0.f, xn = 0.f;
    if (tid < 64) {
        const float* xp0 = g_xp + ((size_t)(kt*M_ + b4*T_))*1536 + c*16 + u;
        xr = __ldg(xp0); xz = __ldg(xp0 + 512); xn = __ldg(xp0 + 1024);
    }

    for (int t = 0; t < T_; ++t) {
        /* poll the 16 payloads this lane consumes (4 producer CTAs) */
        unsigned long long pl[4][4];
        #pragma unroll
        for (int i = 0; i < 4; ++i)
            #pragma unroll
            for (int q = 0; q < 4; ++q) pl[i][q] = 0ull;
        {
            const unsigned long long* hb =
                g_hp + ((size_t)(t & 1) * 4 + kt) * 2048 + (size_t)gid * 512;
            const uint32_t tag = (uint32_t)t;
            for (;;) {
                int ok = 1;
                if (need) {
                    #pragma unroll
                    for (int i = 0; i < 4; ++i) {
                        int k0 = ((w << 2) + i) * 16 + 2 * tig;
                        ldv2(hb + k0,     pl[i][0], pl[i][1]);
                        ldv2(hb + k0 + 8, pl[i][2], pl[i][3]);
                        #pragma unroll
                        for (int q = 0; q < 4; ++q)
                            ok &= ((uint32_t)(pl[i][q] >> 32) == tag);
                    }
                }
                if (__all_sync(0xffffffffu, ok)) break;
            }
        }
        /* consume this step's pipelined xp, issue next step's loads */
        float xr_c = xr, xz_c = xz, xn_c = xn;
        if (tid < 64 && t + 1 < T_) {
            const float* xp = g_xp + ((size_t)(kt*M_ + b4*T_ + t + 1))*1536 + c*16 + u;
            xr = __ldg(xp); xz = __ldg(xp + 512); xn = __ldg(xp + 1024);
        }
        /* fragments + MMAs */
        float acc[3][4];
        #pragma unroll
        for (int g = 0; g < 3; ++g)
            #pragma unroll
            for (int q = 0; q < 4; ++q) acc[g][q] = 0.f;
        #pragma unroll
        for (int i = 0; i < 4; ++i) {
            uint32_t b0 = packh2(__uint_as_float((uint32_t)pl[i][0]),
                                 __uint_as_float((uint32_t)pl[i][1]));
            uint32_t b1 = packh2(__uint_as_float((uint32_t)pl[i][2]),
                                 __uint_as_float((uint32_t)pl[i][3]));
            int ks = (w << 2) + i;
            #pragma unroll
            for (int g = 0; g < 3; ++g) {
                uint4 fr = sAf[(ks*3 + g)*32 + lane];
                MMA_F16(acc[g], fr, b0, b1);
            }
        }
        /* store partials (lanes with real batches: tig<2), parity buffer */
        float* red = sRed + (t & 1) * 1536;
        if (tig < 2) {
            #pragma unroll
            for (int g = 0; g < 3; ++g) {
                int r0 = (g*16 + gid)*4 + 2*tig;
                int r1 = (g*16 + gid + 8)*4 + 2*tig;
                red[(r0  )*8 + w] = acc[g][0];
                red[(r0+1)*8 + w] = acc[g][1];
                red[(r1  )*8 + w] = acc[g][2];
                red[(r1+1)*8 + w] = acc[g][3];
            }
        }

        /* split barrier: producer warps (2-7) arrive and immediately
           proceed to next-step poll; gate warps (0-1) sync.         */
        if (tid >= 64) {
            asm volatile("bar.arrive 1, 256;" ::: "memory");
            continue;
        }
        asm volatile("bar.sync 1, 256;" ::: "memory");

        /* gates + state update (64 threads: tid = b4*16 + u) */
        {
            const float* pr = red + ((u)*4    + b4)*8;
            const float* pz = red + ((16+u)*4 + b4)*8;
            const float* pn = red + ((32+u)*4 + b4)*8;
            float4 r0 = *(const float4*)pr, r1 = *(const float4*)(pr+4);
            float4 z0 = *(const float4*)pz, z1 = *(const float4*)(pz+4);
            float4 n0 = *(const float4*)pn, n1 = *(const float4*)(pn+4);
            float hr = r0.x+r0.y+r0.z+r0.w + r1.x+r1.y+r1.z+r1.w + sBhh[u];
            float hz = z0.x+z0.y+z0.z+z0.w + z1.x+z1.y+z1.z+z1.w + sBhh[16+u];
            float hn = n0.x+n0.y+n0.z+n0.w + n1.x+n1.y+n1.z+n1.w + sBhh[32+u];
            float r = fsig(xr_c + hr);
            float z = fsig(xz_c + hz);
            float ax = xn_c + r * hn;
            float n = 1.f - __fdividef(2.f, __expf(2.f*ax) + 1.f);
            float hnew = (1.f - z) * n + z * hold;
            hold = hnew;
            unsigned long long pay =
                ((unsigned long long)(uint32_t)(t + 1) << 32) |
                (unsigned long long)__float_as_uint(hnew);
            strx(g_hp + ((size_t)((t + 1) & 1) * 4 + kt) * 2048 +
                 (size_t)b4 * 512 + c*16 + u, pay);
            g_comb_h[((size_t)(kt*M_ + b4*T_ + t)) * 1024 + c*16 + u] = __float2half(hnew);
        }
    }
}

/* ----------------- layernorm (+residual) ------------------------ */
__global__ void ln_kernel(const float* __restrict__ inp, const float* __restrict__ res,
                          const float* __restrict__ gg, const float* __restrict__ bb,
                          float* __restrict__ outf, __half* __restrict__ outh, int zdiv)
{
    int row  = blockIdx.x * 8 + (threadIdx.x >> 5);
    int lane = threadIdx.x & 31;
    int z    = zdiv ? (row / zdiv) : 0;
    int rrow = zdiv ? (row % zdiv) : row;
    const float* ip = inp + (size_t)row * 512;
    const float* rp = res + (size_t)rrow * 512;
    float4 v[4];
    float s = 0.f;
    #pragma unroll
    for (int e = 0; e < 4; ++e) {
        float4 a  = *(const float4*)(ip + 4*lane + 128*e);
        float4 r4 = *(const float4*)(rp + 4*lane + 128*e);
        v[e] = make_float4(a.x+r4.x, a.y+r4.y, a.z+r4.z, a.w+r4.w);
        s += v[e].x + v[e].y + v[e].z + v[e].w;
    }
    #pragma unroll
    for (int off = 16; off; off >>= 1) s += __shfl_xor_sync(0xffffffffu, s, off);
    float mean = s * (1.f/512.f);
    float q = 0.f;
    #pragma unroll
    for (int e = 0; e < 4; ++e) {
        float dx = v[e].x-mean, dy = v[e].y-mean, dz = v[e].z-mean, dw = v[e].w-mean;
        q += dx*dx + dy*dy + dz*dz + dw*dw;
    }
    #pragma unroll
    for (int off = 16; off; off >>= 1) q += __shfl_xor_sync(0xffffffffu, q, off);
    float rstd = rsqrtf(q * (1.f/512.f) + 1e-5f);
    const float* gp = gg + (size_t)z*512;
    const float* bp = bb + (size_t)z*512;
    #pragma unroll
    for (int e = 0; e < 4; ++e) {
        float4 g4 = *(const float4*)(gp + 4*lane + 128*e);
        float4 b4 = *(const float4*)(bp + 4*lane + 128*e);
        float4 o;
        o.x = (v[e].x-mean)*rstd*g4.x + b4.x;
        o.y = (v[e].y-mean)*rstd*g4.y + b4.y;
        o.z = (v[e].z-mean)*rstd*g4.z + b4.z;
        o.w = (v[e].w-mean)*rstd*g4.w + b4.w;
        if (outf)
            *(float4*)(outf + (size_t)row*512 + 4*lane + 128*e) = o;
        if (outh) {
            __half2 h0 = __floats2half2_rn(o.x, o.y);
            __half2 h1 = __floats2half2_rn(o.z, o.w);
            *(__half2*)(outh + (size_t)row*512 + 4*lane + 128*e)     = h0;
            *(__half2*)(outh + (size_t)row*512 + 4*lane + 128*e + 2) = h1;
        }
    }
}

/* --------------------------- launch ------------------------------ */
extern "C" void kernel_launch(void* const* d_in, const int* in_sizes, int n_in,
                              void* d_out, int out_size)
{
    const float* x     = (const float*)d_in[0];
    const float* wih   = (const float*)d_in[1];
    const float* whh   = (const float*)d_in[2];
    const float* bih   = (const float*)d_in[3];
    const float* bhh   = (const float*)d_in[4];
    const float* wq    = (const float*)d_in[5];
    const float* wk    = (const float*)d_in[6];
    const float* wv    = (const float*)d_in[7];
    const float* wbeat = (const float*)d_in[8];
    const float* ng    = (const float*)d_in[9];
    const float* nb    = (const float*)d_in[10];
    const float* wmix  = (const float*)d_in[11];
    const float* bng   = (const float*)d_in[12];
    const float* bnb   = (const float*)d_in[13];
    float* out = (float*)d_out;

    float *p_xpe, *p_xp, *p_thr, *p_mix;
    __half *p_xpeh, *p_combh, *p_thrh;
    __half *p_wih, *p_wq, *p_wk, *p_wv, *p_wbt, *p_wmx;
    cudaGetSymbolAddress((void**)&p_xpe,   g_xpe);
    cudaGetSymbolAddress((void**)&p_xpeh,  g_xpe_h);
    cudaGetSymbolAddress((void**)&p_xp,    g_xp);
    cudaGetSymbolAddress((void**)&p_combh, g_comb_h);
    cudaGetSymbolAddress((void**)&p_thr,   g_thr);
    cudaGetSymbolAddress((void**)&p_thrh,  g_thr_h);
    cudaGetSymbolAddress((void**)&p_mix,   g_mix);
    cudaGetSymbolAddress((void**)&p_wih,   g_wih_h);
    cudaGetSymbolAddress((void**)&p_wq,    g_wq_h);
    cudaGetSymbolAddress((void**)&p_wk,    g_wk_h);
    cudaGetSymbolAddress((void**)&p_wv,    g_wv_h);
    cudaGetSymbolAddress((void**)&p_wbt,   g_wbt_h);
    cudaGetSymbolAddress((void**)&p_wmx,   g_wmx_h);

    cudaFuncSetAttribute(gru_kernel,  cudaFuncAttributeMaxDynamicSharedMemorySize, 122880);
    cudaFuncSetAttribute(gemm_kernel, cudaFuncAttributeMaxDynamicSharedMemorySize, 61440);

    init_kernel<<<64, 256>>>();
    pe_add_kernel<<<(T_*D_)/256, 256>>>(x);

    /* weight converts (fp32 -> fp16) */
    f2h_kernel<<<(4*3*D_*D_/4 + 255)/256, 256>>>(wih,   p_wih, 4*3*D_*D_/4);
    f2h_kernel<<<(4*D_*D_/4   + 255)/256, 256>>>(wq,    p_wq,  4*D_*D_/4);
    f2h_kernel<<<(4*D_*D_/4   + 255)/256, 256>>>(wk,    p_wk,  4*D_*D_/4);
    f2h_kernel<<<(4*D_*D_/4   + 255)/256, 256>>>(wv,    p_wv,  4*D_*D_/4);
    f2h_kernel<<<(4*D_*2*D_/4 + 255)/256, 256>>>(wbeat, p_wbt, 4*D_*2*D_/4);
    f2h_kernel<<<(D_*4*D_/4   + 255)/256, 256>>>(wmix,  p_wmx, D_*4*D_/4);

    // xp = wih @ xpe + bih   (M=8192, N=1536, K=512, z=4) — must precede GRU
    gemm_kernel<<<dim3(64,12,4), 256, 61440>>>(p_xpeh, 0, 512, 512,
                                        p_wih, (size_t)1536*512, 512,
                                        bih, 1536,
                                        p_xp, (size_t)M_*1536, 1536);

    /* fat kernel: 128 GRU CTAs + 20 helpers (qkv GEMM -> attn) */
    gru_kernel<<<148, 256, 122880>>>(whh, bhh);

    // beat = w_beat @ comb   (K=1024) -> g_thr (fp32)
    gemm_kernel<<<dim3(64,4,4), 256, 61440>>>(p_combh, (size_t)M_*1024, 1024, 512,
                                       p_wbt, (size_t)512*1024, 1024,
                                       nullptr, 0, p_thr, (size_t)M_*512, 512);
    // thr = LN(beat + xpe) -> fp16
    ln_kernel<<<4096, 256>>>(p_thr, p_xpe, ng, nb, nullptr, p_thrh, 8192);
    // out0 = w_mix @ merged  (K=2048 over the 4 thr chunks)
    gemm_kernel<<<dim3(64,4,1), 256, 61440>>>(p_thrh, 0, 512, (size_t)M_*512,
                                       p_wmx, 0, 2048,
                                       nullptr, 0, p_mix, 0, 512);
    // out = LN(out0 + xpe) -> fp32
    ln_kernel<<<1024, 256>>>(p_mix, p_xpe, bng, bnb, out, nullptr, 0);
}

// round 13
// speedup vs baseline: 1.6179x; 1.0148x over previous
#include <cuda_runtime.h>
#include <cuda_fp16.h>
#include <math.h>
#include <stdint.h>

#define B_ 4
#define T_ 2048
#define D_ 512
#define M_ (B_*T_)   /* 8192 */

/* ------------ static device scratch (no allocations) ------------ */
__device__ float  g_xpe[(size_t)M_*D_];          // x + PE (fp32, residuals)
__device__ __half g_xpe_h[(size_t)M_*D_];        // fp16 GEMM input
__device__ float  g_xp [(size_t)4*M_*3*D_];      // wih @ xpe + bih
__device__ float  g_q  [(size_t)4*M_*D_];
__device__ float  g_kk [(size_t)4*M_*D_];
__device__ float  g_v  [(size_t)4*M_*D_];
__device__ __half g_comb_h[(size_t)4*M_*2*D_];   // [gru | attn] fp16
__device__ float  g_thr[(size_t)4*M_*D_];        // beat (fp32 GEMM out)
__device__ __half g_thr_h[(size_t)4*M_*D_];      // LN(beat+xpe) fp16
__device__ float  g_mix[(size_t)M_*D_];
/* fp16 weights */
__device__ __half g_wih_h [(size_t)4*3*D_*D_];
__device__ __half g_wq_h  [(size_t)4*D_*D_];
__device__ __half g_wk_h  [(size_t)4*D_*D_];
__device__ __half g_wv_h  [(size_t)4*D_*D_];
__device__ __half g_wbt_h [(size_t)4*D_*2*D_];
__device__ __half g_wmx_h [(size_t)D_*4*D_];
/* hidden-state payloads: (tag<<32 | f32 bits), [2 buf][4 kt][4 b][512 j] */
__device__ __align__(128) unsigned long long g_hp[2*4*4*512];
__device__ int g_hctr;                           // helper qkv-done counter

__device__ __forceinline__ uint32_t packh2(float lo, float hi) {
    uint32_t d; asm("cvt.rn.f16x2.f32 %0, %1, %2;" : "=r"(d) : "f"(hi), "f"(lo));
    return d;
}
__device__ __forceinline__ float fsig(float x) {
    return __fdividef(1.f, 1.f + __expf(-x));
}
__device__ __forceinline__ void cp16(void* s, const void* g) {
    uint32_t a = (uint32_t)__cvta_generic_to_shared(s);
    asm volatile("cp.async.cg.shared.global [%0], [%1], 16;" :: "r"(a), "l"(g));
}
__device__ __forceinline__ void ldv2(const unsigned long long* p,
                                     unsigned long long& a, unsigned long long& b) {
    asm volatile("ld.volatile.global.v2.u64 {%0,%1}, [%2];"
                 : "=l"(a), "=l"(b) : "l"(p) : "memory");
}
__device__ __forceinline__ void strx(unsigned long long* p, unsigned long long v) {
    asm volatile("st.relaxed.gpu.global.b64 [%0], %1;" :: "l"(p), "l"(v) : "memory");
}
__device__ __forceinline__ int ldacq(const int* p) {
    int v; asm volatile("ld.acquire.gpu.global.b32 %0, [%1];" : "=r"(v) : "l"(p) : "memory");
    return v;
}
__device__ __forceinline__ void ldsm4(uint32_t& r0, uint32_t& r1, uint32_t& r2, uint32_t& r3,
                                      const void* smem_ptr) {
    uint32_t a = (uint32_t)__cvta_generic_to_shared(smem_ptr);
    asm volatile("ldmatrix.sync.aligned.m8n8.x4.shared.b16 {%0,%1,%2,%3}, [%4];"
                 : "=r"(r0), "=r"(r1), "=r"(r2), "=r"(r3) : "r"(a));
}
#define MMA_F16A(C, A0, A1, A2, A3, B0, B1) \
    asm volatile("mma.sync.aligned.m16n8k16.row.col.f32.f16.f16.f32 " \
        "{%0,%1,%2,%3},{%4,%5,%6,%7},{%8,%9},{%0,%1,%2,%3};" \
        : "+f"((C)[0]), "+f"((C)[1]), "+f"((C)[2]), "+f"((C)[3]) \
        : "r"(A0), "r"(A1), "r"(A2), "r"(A3), "r"(B0), "r"(B1))
#define MMA_F16(C, FR, B0, B1) MMA_F16A(C, (FR).x, (FR).y, (FR).z, (FR).w, B0, B1)

/* ---------------------------- init ------------------------------ */
__global__ void init_kernel() {
    int i = blockIdx.x * 256 + threadIdx.x;
    if (i < 2*4*4*512) g_hp[i] = 0ull;
    if (i == 0) g_hctr = 0;
}

/* ---------- f32 -> f16 convert, all 6 weights in one launch ------ */
__global__ void f2h_all_kernel(const float* __restrict__ wih, const float* __restrict__ wq,
                               const float* __restrict__ wk,  const float* __restrict__ wv,
                               const float* __restrict__ wbt, const float* __restrict__ wmx)
{
    /* segment sizes in float4 units */
    const int n_wih = 4*3*D_*D_/4;   /* 786432 */
    const int n_sq  = 4*D_*D_/4;     /* 262144 */
    const int n_wbt = 4*D_*2*D_/4;   /* 524288 */
    const int n_wmx = D_*4*D_/4;     /* 262144 */
    int i = blockIdx.x * 256 + threadIdx.x;
    const float* src; __half* dst; int off;
    if (i < n_wih)                         { src = wih; dst = g_wih_h; off = i; }
    else if ((i -= n_wih) < n_sq)          { src = wq;  dst = g_wq_h;  off = i; }
    else if ((i -= n_sq)  < n_sq)          { src = wk;  dst = g_wk_h;  off = i; }
    else if ((i -= n_sq)  < n_sq)          { src = wv;  dst = g_wv_h;  off = i; }
    else if ((i -= n_sq)  < n_wbt)         { src = wbt; dst = g_wbt_h; off = i; }
    else if ((i -= n_wbt) < n_wmx)         { src = wmx; dst = g_wmx_h; off = i; }
    else return;
    float4 v = ((const float4*)src)[off];
    ((__half2*)dst)[2*off]   = __floats2half2_rn(v.x, v.y);
    ((__half2*)dst)[2*off+1] = __floats2half2_rn(v.z, v.w);
}

/* -------------------- positional encoding ----------------------- */
__global__ void pe_add_kernel(const float* __restrict__ x) {
    int idx = blockIdx.x * 256 + threadIdx.x;   // 0 .. T*D-1
    int t = idx >> 9;
    int d = idx & 511;
    const float kfac = -9.210340371976184f / 512.0f;
    float dv  = expf((float)(d & ~1) * kfac);
    float arg = (float)t * dv;
    float pe  = (d & 1) ? cosf(arg) : sinf(arg);
    int slot = d >> 7;
    int off  = d & 127;
    int c    = 5 + slot;
    float ph = ((float)(t % c) / (float)c) * 6.283185307179586f;
    float tv = (off < 64) ? sinf(ph * (float)(off + 1)) : cosf(ph * (float)(off - 63));
    float tot = 0.5f * pe + 0.5f * tv;
    #pragma unroll
    for (int b = 0; b < B_; ++b) {
        float v = x[(size_t)b*(T_*D_) + idx] + tot;
        g_xpe  [(size_t)b*(T_*D_) + idx] = v;
        g_xpe_h[(size_t)b*(T_*D_) + idx] = __float2half(v);
    }
}

/* --------- fp16 tensor-core NT GEMM body, cp.async 3-stage,
   ldmatrix fragment loads. Tiles [row][40-half pitch].            */
__device__ void gemm_body(const __half* __restrict__ Az, size_t sAm, size_t sAchunk,
                          const __half* __restrict__ Wz, int K,
                          const float* __restrict__ biasz,
                          float* __restrict__ Cz, size_t sCm,
                          int m0, int n0, __half* hsm, int tid)
{
    __half* As0 = hsm;             // [3][128][40]
    __half* Bs0 = hsm + 15360;
#define AS(s,r,k) As0[(s)*5120 + (r)*40 + (k)]
#define BS(s,r,k) Bs0[(s)*5120 + (r)*40 + (k)]
    const int hr = tid >> 1;
    const int hc = (tid & 1) * 16;
    const int warp = tid >> 5;
    const int lane = tid & 31;
    const int wm = warp >> 1;
    const int wn = warp & 1;
    const int gid = lane >> 2;
    const int tig = lane & 3;

    /* ldmatrix per-lane address components */
    const int la   = lane & 7;
    const int rA   = wm*32 + ((lane >> 3) & 1)*8 + la;   /* + mf*16 */
    const int cA   = ((lane >> 4) & 1)*8;                /* + kb    */
    const int rB   = wn*64 + ((lane >> 4) & 1)*8 + la;   /* + 2j*8  */
    const int cB   = ((lane >> 3) & 1)*8;                /* + kb    */

    float acc[2][8][4];
    #pragma unroll
    for (int mf = 0; mf < 2; ++mf)
        #pragma unroll
        for (int nf = 0; nf < 8; ++nf)
            #pragma unroll
            for (int q = 0; q < 4; ++q) acc[mf][nf][q] = 0.f;

    const int nt = K >> 5;
    {
        const __half* ap = Az + (size_t)(m0 + hr) * sAm + hc;
        cp16(&AS(0,hr,hc), ap); cp16(&AS(0,hr,hc+8), ap + 8);
        const __half* wp = Wz + (size_t)(n0 + hr) * K + hc;
        cp16(&BS(0,hr,hc), wp); cp16(&BS(0,hr,hc+8), wp + 8);
        asm volatile("cp.async.commit_group;");
    }
    if (nt > 1) {
        const __half* ap = Az + (size_t)(m0 + hr) * sAm + 32 + hc;
        cp16(&AS(1,hr,hc), ap); cp16(&AS(1,hr,hc+8), ap + 8);
        const __half* wp = Wz + (size_t)(n0 + hr) * K + 32 + hc;
        cp16(&BS(1,hr,hc), wp); cp16(&BS(1,hr,hc+8), wp + 8);
        asm volatile("cp.async.commit_group;");
    }
    for (int kt = 0; kt < nt; ++kt) {
        if (kt + 1 < nt) asm volatile("cp.async.wait_group 1;");
        else             asm volatile("cp.async.wait_group 0;");
        __syncthreads();
        if (kt + 2 < nt) {
            int j0 = (kt + 2) * 32;
            int ps = (kt + 2) % 3;
            const __half* ap = Az + (size_t)(m0 + hr) * sAm + (size_t)(j0 >> 9) * sAchunk + (j0 & 511) + hc;
            cp16(&AS(ps,hr,hc), ap); cp16(&AS(ps,hr,hc+8), ap + 8);
            const __half* wp = Wz + (size_t)(n0 + hr) * K + j0 + hc;
            cp16(&BS(ps,hr,hc), wp); cp16(&BS(ps,hr,hc+8), wp + 8);
            asm volatile("cp.async.commit_group;");
        }
        const int s = kt % 3;
        #pragma unroll
        for (int ks = 0; ks < 2; ++ks) {
            const int kb = ks * 16;
            uint32_t af[2][4];
            #pragma unroll
            for (int mf = 0; mf < 2; ++mf)
                ldsm4(af[mf][0], af[mf][1], af[mf][2], af[mf][3],
                      &AS(s, rA + mf*16, kb + cA));
            #pragma unroll
            for (int j = 0; j < 4; ++j) {
                uint32_t q0, q1, q2, q3;   /* b0[2j], b1[2j], b0[2j+1], b1[2j+1] */
                ldsm4(q0, q1, q2, q3, &BS(s, rB + j*16, kb + cB));
                MMA_F16A(acc[0][2*j],   af[0][0], af[0][1], af[0][2], af[0][3], q0, q1);
                MMA_F16A(acc[1][2*j],   af[1][0], af[1][1], af[1][2], af[1][3], q0, q1);
                MMA_F16A(acc[0][2*j+1], af[0][0], af[0][1], af[0][2], af[0][3], q2, q3);
                MMA_F16A(acc[1][2*j+1], af[1][0], af[1][1], af[1][2], af[1][3], q2, q3);
            }
        }
    }

    #pragma unroll
    for (int mf = 0; mf < 2; ++mf) {
        int r0 = m0 + wm*32 + mf*16 + gid;
        #pragma unroll
        for (int nf = 0; nf < 8; ++nf) {
            int col = n0 + wn*64 + nf*8 + 2*tig;
            float bb0 = 0.f, bb1 = 0.f;
            if (biasz) {
                bb0 = biasz[col];
                bb1 = biasz[col + 1];
            }
            float2 o0 = make_float2(acc[mf][nf][0] + bb0, acc[mf][nf][1] + bb1);
            float2 o1 = make_float2(acc[mf][nf][2] + bb0, acc[mf][nf][3] + bb1);
            *(float2*)(Cz + (size_t)r0      * sCm + col) = o0;
            *(float2*)(Cz + (size_t)(r0+8)  * sCm + col) = o1;
        }
    }
#undef AS
#undef BS
}

__global__ void __launch_bounds__(256)
gemm_kernel(const __half* __restrict__ A, size_t sAz, size_t sAm, size_t sAchunk,
            const __half* __restrict__ W, size_t sWz, int K,
            const float* __restrict__ bias, size_t sBz,
            float* __restrict__ C, size_t sCz, size_t sCm)
{
    extern __shared__ __half hsm[];
    const int z = blockIdx.z;
    gemm_body(A + (size_t)z * sAz, sAm, sAchunk,
              W + (size_t)z * sWz, K,
              bias ? bias + (size_t)z * sBz : nullptr,
              C + (size_t)z * sCz, sCm,
              blockIdx.x * 128, blockIdx.y * 128, hsm, threadIdx.x);
}

/* ------------------ attention body (device fn) ------------------ */
__device__ void attn_body(int gw, int lane) {
    int t  = gw & (T_ - 1);
    int kb = gw >> 11;
    int b  = kb & 3;
    int kt = kb >> 2;
    int c  = 5 + kt;
    int L  = min(c, t + 1);
    size_t rowbase = (size_t)kt * M_ + (size_t)b * T_;
    const float* qp = g_q + (rowbase + t) * D_;
    float4 qv[4];
    #pragma unroll
    for (int e = 0; e < 4; ++e) qv[e] = *(const float4*)(qp + 4*lane + 128*e);

    float sc[8];
    float smax = -1e30f;
    #pragma unroll
    for (int s0 = 0; s0 < 8; ++s0) {
        if (s0 < L) {
            const float* kp = g_kk + (rowbase + t - s0) * D_;
            float a = 0.f;
            #pragma unroll
            for (int e = 0; e < 4; ++e) {
                float4 kv = *(const float4*)(kp + 4*lane + 128*e);
                a += qv[e].x*kv.x + qv[e].y*kv.y + qv[e].z*kv.z + qv[e].w*kv.w;
            }
            #pragma unroll
            for (int off = 16; off; off >>= 1) a += __shfl_xor_sync(0xffffffffu, a, off);
            a *= 0.044194173824159216f;
            sc[s0] = a;
            smax = fmaxf(smax, a);
        }
    }
    float denom = 0.f;
    float4 acc[4];
    #pragma unroll
    for (int e = 0; e < 4; ++e) acc[e] = make_float4(0.f, 0.f, 0.f, 0.f);
    #pragma unroll
    for (int s0 = 0; s0 < 8; ++s0) {
        if (s0 < L) {
            float p = expf(sc[s0] - smax);
            denom += p;
            const float* vp = g_v + (rowbase + t - s0) * D_;
            #pragma unroll
            for (int e = 0; e < 4; ++e) {
                float4 vv = *(const float4*)(vp + 4*lane + 128*e);
                acc[e].x += p*vv.x; acc[e].y += p*vv.y;
                acc[e].z += p*vv.z; acc[e].w += p*vv.w;
            }
        }
    }
    float inv = 1.f / denom;
    __half* op = g_comb_h + (rowbase + t) * 1024 + 512;
    #pragma unroll
    for (int e = 0; e < 4; ++e) {
        __half2 h0 = __floats2half2_rn(acc[e].x*inv, acc[e].y*inv);
        __half2 h1 = __floats2half2_rn(acc[e].z*inv, acc[e].w*inv);
        *(__half2*)(op + 4*lane + 128*e)     = h0;
        *(__half2*)(op + 4*lane + 128*e + 2) = h1;
    }
}

/* ------------------- fat kernel: GRU + qkv + attn ---------------- */
__global__ void __launch_bounds__(256, 1)
gru_kernel(const float* __restrict__ whh, const float* __restrict__ bhh)
{
    extern __shared__ float sm[];
    const int tid  = threadIdx.x;
    const int lane = tid & 31;
    const int w    = tid >> 5;

    if (blockIdx.x >= 128) {                 /* ---- helpers ---- */
        int helper = blockIdx.x - 128;       /* 0..19 */
        __half* hsm = (__half*)sm;
        /* qkv: 3 gemms x (64 m x 4 n x 4 z) = 3072 tiles */
        for (int job = helper; job < 3072; job += 20) {
            int which = job / 1024;
            int rem   = job & 1023;
            int z     = rem >> 8;
            int mn    = rem & 255;
            const __half* Wsel = (which == 0) ? g_wq_h : (which == 1) ? g_wk_h : g_wv_h;
            float*        Csel = (which == 0) ? g_q    : (which == 1) ? g_kk   : g_v;
            gemm_body(g_xpe_h, 512, 0,
                      Wsel + (size_t)z*512*512, 512, nullptr,
                      Csel + (size_t)z*M_*512, 512,
                      (mn >> 2) * 128, (mn & 3) * 128, hsm, tid);
            __syncthreads();
        }
        /* publish qkv, wait for all 20 helpers */
        __threadfence();
        __syncthreads();
        if (tid == 0) {
            atomicAdd(&g_hctr, 1);
            while (ldacq(&g_hctr) < 20) { }
        }
        __syncthreads();
        for (int job = helper; job < 4096; job += 20)
            attn_body(job * 8 + w, lane);
        return;
    }

    uint4* sAf  = (uint4*)sm;          // 3072 x 16B = 49152B
    float* sRed = sm + 12288;          // [2][48 rows][4 b][8 warps]
    float* sBhh = sm + 12288 + 3072;   // 48

    const int kt   = blockIdx.x >> 5;
    const int c    = blockIdx.x & 31;
    const int gid  = lane >> 2;
    const int tig  = lane & 3;

    /* ---- one-time: build fp16 A fragments from whh ---- */
    const float* wkp = whh + (size_t)kt * (1536*512);
    for (int e = tid; e < 3072; e += 256) {
        int el = e & 31;
        int g  = (e >> 5) % 3;
        int ks = e / 96;
        int eg = el >> 2, et = el & 3;
        const float* w0 = wkp + (size_t)(g*512 + c*16 + eg) * 512;
        const float* w1 = w0 + 8*512;
        int k0 = ks*16 + 2*et;
        float2 p0 = *(const float2*)(w0 + k0);
        float2 p1 = *(const float2*)(w1 + k0);
        float2 p2 = *(const float2*)(w0 + k0 + 8);
        float2 p3 = *(const float2*)(w1 + k0 + 8);
        uint4 fr;
        fr.x = packh2(p0.x, p0.y);
        fr.y = packh2(p1.x, p1.y);
        fr.z = packh2(p2.x, p2.y);
        fr.w = packh2(p3.x, p3.y);
        sAf[e] = fr;
    }
    if (tid < 48) {
        int g = tid >> 4, u2 = tid & 15;
        sBhh[tid] = bhh[kt*1536 + g*512 + c*16 + u2];
    }
    __syncthreads();

    const int u  = tid & 15;
    const int b4 = tid >> 4;
    const int need = (gid < 4);
    float hold = 0.f;

    /* xp pipeline: preload step 0 */
    float xr = 0.f, xz = 0.f, xn = 0.f;
    if (tid < 64) {
        const float* xp0 = g_xp + ((size_t)(kt*M_ + b4*T_))*1536 + c*16 + u;
        xr = __ldg(xp0); xz = __ldg(xp0 + 512); xn = __ldg(xp0 + 1024);
    }

    for (int t = 0; t < T_; ++t) {
        /* poll the 16 payloads this lane consumes (4 producer CTAs) */
        unsigned long long pl[4][4];
        #pragma unroll
        for (int i = 0; i < 4; ++i)
            #pragma unroll
            for (int q = 0; q < 4; ++q) pl[i][q] = 0ull;
        {
            const unsigned long long* hb =
                g_hp + ((size_t)(t & 1) * 4 + kt) * 2048 + (size_t)gid * 512;
            const uint32_t tag = (uint32_t)t;
            for (;;) {
                int ok = 1;
                if (need) {
                    #pragma unroll
                    for (int i = 0; i < 4; ++i) {
                        int k0 = ((w << 2) + i) * 16 + 2 * tig;
                        ldv2(hb + k0,     pl[i][0], pl[i][1]);
                        ldv2(hb + k0 + 8, pl[i][2], pl[i][3]);
                        #pragma unroll
                        for (int q = 0; q < 4; ++q)
                            ok &= ((uint32_t)(pl[i][q] >> 32) == tag);
                    }
                }
                if (__all_sync(0xffffffffu, ok)) break;
            }
        }
        /* consume this step's pipelined xp, issue next step's loads */
        float xr_c = xr, xz_c = xz, xn_c = xn;
        if (tid < 64 && t + 1 < T_) {
            const float* xp = g_xp + ((size_t)(kt*M_ + b4*T_ + t + 1))*1536 + c*16 + u;
            xr = __ldg(xp); xz = __ldg(xp + 512); xn = __ldg(xp + 1024);
        }
        /* fragments + MMAs */
        float acc[3][4];
        #pragma unroll
        for (int g = 0; g < 3; ++g)
            #pragma unroll
            for (int q = 0; q < 4; ++q) acc[g][q] = 0.f;
        #pragma unroll
        for (int i = 0; i < 4; ++i) {
            uint32_t b0 = packh2(__uint_as_float((uint32_t)pl[i][0]),
                                 __uint_as_float((uint32_t)pl[i][1]));
            uint32_t b1 = packh2(__uint_as_float((uint32_t)pl[i][2]),
                                 __uint_as_float((uint32_t)pl[i][3]));
            int ks = (w << 2) + i;
            #pragma unroll
            for (int g = 0; g < 3; ++g) {
                uint4 fr = sAf[(ks*3 + g)*32 + lane];
                MMA_F16(acc[g], fr, b0, b1);
            }
        }
        /* store partials (lanes with real batches: tig<2), parity buffer */
        float* red = sRed + (t & 1) * 1536;
        if (tig < 2) {
            #pragma unroll
            for (int g = 0; g < 3; ++g) {
                int r0 = (g*16 + gid)*4 + 2*tig;
                int r1 = (g*16 + gid + 8)*4 + 2*tig;
                red[(r0  )*8 + w] = acc[g][0];
                red[(r0+1)*8 + w] = acc[g][1];
                red[(r1  )*8 + w] = acc[g][2];
                red[(r1+1)*8 + w] = acc[g][3];
            }
        }

        /* split barrier: producer warps (2-7) arrive and immediately
           proceed to next-step poll; gate warps (0-1) sync.         */
        if (tid >= 64) {
            asm volatile("bar.arrive 1, 256;" ::: "memory");
            continue;
        }
        asm volatile("bar.sync 1, 256;" ::: "memory");

        /* gates + state update (64 threads: tid = b4*16 + u) */
        {
            const float* pr = red + ((u)*4    + b4)*8;
            const float* pz = red + ((16+u)*4 + b4)*8;
            const float* pn = red + ((32+u)*4 + b4)*8;
            float4 r0 = *(const float4*)pr, r1 = *(const float4*)(pr+4);
            float4 z0 = *(const float4*)pz, z1 = *(const float4*)(pz+4);
            float4 n0 = *(const float4*)pn, n1 = *(const float4*)(pn+4);
            float hr = r0.x+r0.y+r0.z+r0.w + r1.x+r1.y+r1.z+r1.w + sBhh[u];
            float hz = z0.x+z0.y+z0.z+z0.w + z1.x+z1.y+z1.z+z1.w + sBhh[16+u];
            float hn = n0.x+n0.y+n0.z+n0.w + n1.x+n1.y+n1.z+n1.w + sBhh[32+u];
            float r = fsig(xr_c + hr);
            float z = fsig(xz_c + hz);
            float ax = xn_c + r * hn;
            float n = 1.f - __fdividef(2.f, __expf(2.f*ax) + 1.f);
            float hnew = (1.f - z) * n + z * hold;
            hold = hnew;
            unsigned long long pay =
                ((unsigned long long)(uint32_t)(t + 1) << 32) |
                (unsigned long long)__float_as_uint(hnew);
            strx(g_hp + ((size_t)((t + 1) & 1) * 4 + kt) * 2048 +
                 (size_t)b4 * 512 + c*16 + u, pay);
            g_comb_h[((size_t)(kt*M_ + b4*T_ + t)) * 1024 + c*16 + u] = __float2half(hnew);
        }
    }
}

/* ----------------- layernorm (+residual) ------------------------ */
__global__ void ln_kernel(const float* __restrict__ inp, const float* __restrict__ res,
                          const float* __restrict__ gg, const float* __restrict__ bb,
                          float* __restrict__ outf, __half* __restrict__ outh, int zdiv)
{
    int row  = blockIdx.x * 8 + (threadIdx.x >> 5);
    int lane = threadIdx.x & 31;
    int z    = zdiv ? (row / zdiv) : 0;
    int rrow = zdiv ? (row % zdiv) : row;
    const float* ip = inp + (size_t)row * 512;
    const float* rp = res + (size_t)rrow * 512;
    float4 v[4];
    float s = 0.f;
    #pragma unroll
    for (int e = 0; e < 4; ++e) {
        float4 a  = *(const float4*)(ip + 4*lane + 128*e);
        float4 r4 = *(const float4*)(rp + 4*lane + 128*e);
        v[e] = make_float4(a.x+r4.x, a.y+r4.y, a.z+r4.z, a.w+r4.w);
        s += v[e].x + v[e].y + v[e].z + v[e].w;
    }
    #pragma unroll
    for (int off = 16; off; off >>= 1) s += __shfl_xor_sync(0xffffffffu, s, off);
    float mean = s * (1.f/512.f);
    float q = 0.f;
    #pragma unroll
    for (int e = 0; e < 4; ++e) {
        float dx = v[e].x-mean, dy = v[e].y-mean, dz = v[e].z-mean, dw = v[e].w-mean;
        q += dx*dx + dy*dy + dz*dz + dw*dw;
    }
    #pragma unroll
    for (int off = 16; off; off >>= 1) q += __shfl_xor_sync(0xffffffffu, q, off);
    float rstd = rsqrtf(q * (1.f/512.f) + 1e-5f);
    const float* gp = gg + (size_t)z*512;
    const float* bp = bb + (size_t)z*512;
    #pragma unroll
    for (int e = 0; e < 4; ++e) {
        float4 g4 = *(const float4*)(gp + 4*lane + 128*e);
        float4 b4 = *(const float4*)(bp + 4*lane + 128*e);
        float4 o;
        o.x = (v[e].x-mean)*rstd*g4.x + b4.x;
        o.y = (v[e].y-mean)*rstd*g4.y + b4.y;
        o.z = (v[e].z-mean)*rstd*g4.z + b4.z;
        o.w = (v[e].w-mean)*rstd*g4.w + b4.w;
        if (outf)
            *(float4*)(outf + (size_t)row*512 + 4*lane + 128*e) = o;
        if (outh) {
            __half2 h0 = __floats2half2_rn(o.x, o.y);
            __half2 h1 = __floats2half2_rn(o.z, o.w);
            *(__half2*)(outh + (size_t)row*512 + 4*lane + 128*e)     = h0;
            *(__half2*)(outh + (size_t)row*512 + 4*lane + 128*e + 2) = h1;
        }
    }
}

/* --------------------------- launch ------------------------------ */
extern "C" void kernel_launch(void* const* d_in, const int* in_sizes, int n_in,
                              void* d_out, int out_size)
{
    const float* x     = (const float*)d_in[0];
    const float* wih   = (const float*)d_in[1];
    const float* whh   = (const float*)d_in[2];
    const float* bih   = (const float*)d_in[3];
    const float* bhh   = (const float*)d_in[4];
    const float* wq    = (const float*)d_in[5];
    const float* wk    = (const float*)d_in[6];
    const float* wv    = (const float*)d_in[7];
    const float* wbeat = (const float*)d_in[8];
    const float* ng    = (const float*)d_in[9];
    const float* nb    = (const float*)d_in[10];
    const float* wmix  = (const float*)d_in[11];
    const float* bng   = (const float*)d_in[12];
    const float* bnb   = (const float*)d_in[13];
    float* out = (float*)d_out;

    float *p_xpe, *p_xp, *p_thr, *p_mix;
    __half *p_xpeh, *p_combh, *p_thrh;
    __half *p_wih, *p_wbt, *p_wmx;
    cudaGetSymbolAddress((void**)&p_xpe,   g_xpe);
    cudaGetSymbolAddress((void**)&p_xpeh,  g_xpe_h);
    cudaGetSymbolAddress((void**)&p_xp,    g_xp);
    cudaGetSymbolAddress((void**)&p_combh, g_comb_h);
    cudaGetSymbolAddress((void**)&p_thr,   g_thr);
    cudaGetSymbolAddress((void**)&p_thrh,  g_thr_h);
    cudaGetSymbolAddress((void**)&p_mix,   g_mix);
    cudaGetSymbolAddress((void**)&p_wih,   g_wih_h);
    cudaGetSymbolAddress((void**)&p_wbt,   g_wbt_h);
    cudaGetSymbolAddress((void**)&p_wmx,   g_wmx_h);

    cudaFuncSetAttribute(gru_kernel,  cudaFuncAttributeMaxDynamicSharedMemorySize, 122880);
    cudaFuncSetAttribute(gemm_kernel, cudaFuncAttributeMaxDynamicSharedMemorySize, 61440);

    init_kernel<<<64, 256>>>();
    pe_add_kernel<<<(T_*D_)/256, 256>>>(x);

    /* all weight converts (fp32 -> fp16) in one launch: 2359296 float4s */
    f2h_all_kernel<<<(2359296 + 255)/256, 256>>>(wih, wq, wk, wv, wbeat, wmix);

    // xp = wih @ xpe + bih   (M=8192, N=1536, K=512, z=4) — must precede GRU
    gemm_kernel<<<dim3(64,12,4), 256, 61440>>>(p_xpeh, 0, 512, 512,
                                        p_wih, (size_t)1536*512, 512,
                                        bih, 1536,
                                        p_xp, (size_t)M_*1536, 1536);

    /* fat kernel: 128 GRU CTAs + 20 helpers (qkv GEMM -> attn) */
    gru_kernel<<<148, 256, 122880>>>(whh, bhh);

    // beat = w_beat @ comb   (K=1024) -> g_thr (fp32)
    gemm_kernel<<<dim3(64,4,4), 256, 61440>>>(p_combh, (size_t)M_*1024, 1024, 512,
                                       p_wbt, (size_t)512*1024, 1024,
                                       nullptr, 0, p_thr, (size_t)M_*512, 512);
    // thr = LN(beat + xpe) -> fp16
    ln_kernel<<<4096, 256>>>(p_thr, p_xpe, ng, nb, nullptr, p_thrh, 8192);
    // out0 = w_mix @ merged  (K=2048 over the 4 thr chunks)
    gemm_kernel<<<dim3(64,4,1), 256, 61440>>>(p_thrh, 0, 512, (size_t)M_*512,
                                       p_wmx, 0, 2048,
                                       nullptr, 0, p_mix, 0, 512);
    // out = LN(out0 + xpe) -> fp32
    ln_kernel<<<1024, 256>>>(p_mix, p_xpe, bng, bnb, out, nullptr, 0);
}